// round 8
// baseline (speedup 1.0000x reference)
#include <cuda_runtime.h>
#include <math.h>

#define BB 32
#define NN 64
#define KK 128
#define NPAIR (BB*NN*NN)   // 131072
#define NNODE (BB*NN)      // 2048

// ---------------- scratch (no cudaMalloc allowed) ----------------
__device__ float g_rad[NPAIR*8];
__device__ float g_Y[NPAIR*8];
__device__ float g_mask[NPAIR];
__device__ float g_h1[NNODE*KK];
__device__ float g_s1[NNODE*KK];
__device__ float g_v1[NNODE*3*KK];
__device__ float g_s2[NNODE*KK];

__device__ __forceinline__ float siluf(float x) { return x / (1.0f + __expf(-x)); }

typedef unsigned long long u64;
__device__ __forceinline__ u64 pk2(float lo, float hi) {
    u64 r; asm("mov.b64 %0, {%1,%2};" : "=l"(r) : "f"(lo), "f"(hi)); return r;
}
__device__ __forceinline__ void fma2(u64& a, u64 x, u64 y) {
    asm("fma.rn.f32x2 %0, %1, %2, %3;" : "=l"(a) : "l"(x), "l"(y), "l"(a));
}
__device__ __forceinline__ float2 upk(u64 v) {
    float2 o; asm("mov.b64 {%0,%1}, %2;" : "=f"(o.x), "=f"(o.y) : "l"(v)); return o;
}

// ---------------- kernel 1: pairwise geometry ----------------
__global__ void k_geom(const float* __restrict__ frac, const float* __restrict__ cell)
{
    int idx = blockIdx.x * blockDim.x + threadIdx.x;
    if (idx >= NPAIR) return;
    int b = idx >> 12;
    int i = (idx >> 6) & 63;
    int j = idx & 63;
    const float* fi = frac + (b*NN + i)*3;
    const float* fj = frac + (b*NN + j)*3;
    float d0 = fi[0]-fj[0], d1 = fi[1]-fj[1], d2 = fi[2]-fj[2];
    d0 -= rintf(d0); d1 -= rintf(d1); d2 -= rintf(d2);
    const float* C = cell + b*9;
    float x = d0*C[0] + d1*C[3] + d2*C[6];
    float y = d0*C[1] + d1*C[4] + d2*C[7];
    float z = d0*C[2] + d1*C[5] + d2*C[8];
    float r2 = fmaxf(x*x + y*y + z*z, 1e-12f);
    float r = sqrtf(r2);
    bool m = (r < 5.0f) && (i != j);
    float mf = m ? 1.0f : 0.0f;
    float rs = m ? r : 1.0f;
    float inv = 1.0f / rs;
    float ux = x*inv*mf, uy = y*inv*mf, uz = z*inv*mf;
    float u = rs * 0.2f;
    float u2 = u*u, u4 = u2*u2, u5 = u4*u;
    float fc = 1.0f - 21.0f*u5 + 35.0f*u5*u - 15.0f*u5*u2;
    fc = (u < 1.0f) ? fc : 0.0f;
    float pref = 0.6324555320336759f * inv * fc * mf;
    float w = 0.6283185307179586f * rs;
    float* rp = g_rad + (size_t)idx*8;
    #pragma unroll
    for (int n = 1; n <= 8; ++n) rp[n-1] = pref * sinf((float)n * w);
    const float s3 = 1.7320508075688772f, s5 = 2.23606797749979f, s15 = 3.872983346207417f;
    float* Y = g_Y + (size_t)idx*8;
    Y[0] = s3*ux; Y[1] = s3*uy; Y[2] = s3*uz;
    Y[3] = s15*ux*uy;
    Y[4] = s15*uy*uz;
    Y[5] = 0.5f*s5*(3.0f*uz*uz - 1.0f);
    Y[6] = s15*ux*uz;
    Y[7] = 0.5f*s15*(ux*ux - uy*uy);
    g_mask[idx] = mf;
}

// ---------------- 64-wide dense layer, 128 threads, 2j x 16h blocking ----------------
// In: [64][ISTR] smem, W: [CDIM][64] smem, bias gmem, Out: [64][66] smem (silu)
// NOTE: even rows (j0) are 16B-aligned (132m floats) -> float4 stores OK;
//       odd rows ((j0+1)*66) are only 8B-aligned -> float2 stores.
template<int CDIM, int ISTR>
__device__ __forceinline__ void dl128(const float* __restrict__ In,
                                      const float* __restrict__ W,
                                      const float* __restrict__ bias,
                                      float* __restrict__ Out, int t)
{
    int j0 = (t >> 2) * 2;
    int h0 = (t & 3) * 16;
    float acc0[16], acc1[16];
    #pragma unroll
    for (int i = 0; i < 16; ++i) { float bv = bias[h0+i]; acc0[i] = bv; acc1[i] = bv; }
    const float* in0 = In + j0*ISTR;
    const float* in1 = In + (j0+1)*ISTR;
    #pragma unroll 4
    for (int c = 0; c < CDIM; ++c) {
        float a0 = in0[c];
        float a1 = in1[c];
        float wv[16];
        const float4* wr = (const float4*)(W + c*64 + h0);
        *(float4*)(wv)    = wr[0];
        *(float4*)(wv+4)  = wr[1];
        *(float4*)(wv+8)  = wr[2];
        *(float4*)(wv+12) = wr[3];
        #pragma unroll
        for (int i = 0; i < 16; ++i) { acc0[i] += a0*wv[i]; acc1[i] += a1*wv[i]; }
    }
    #pragma unroll
    for (int i = 0; i < 16; i += 4) {
        float4 o0;
        o0.x = siluf(acc0[i]);   o0.y = siluf(acc0[i+1]);
        o0.z = siluf(acc0[i+2]); o0.w = siluf(acc0[i+3]);
        *(float4*)(Out + j0*66 + h0 + i) = o0;
        float2 o1a, o1b;
        o1a.x = siluf(acc1[i]);   o1a.y = siluf(acc1[i+1]);
        o1b.x = siluf(acc1[i+2]); o1b.y = siluf(acc1[i+3]);
        *(float2*)(Out + (j0+1)*66 + h0 + i)     = o1a;
        *(float2*)(Out + (j0+1)*66 + h0 + i + 2) = o1b;
    }
}

// ---------------- kernel 2: phase 1 (128 threads) ----------------
__global__ void __launch_bounds__(128) k_phase1(
    const float* __restrict__ w_embed,
    const float* __restrict__ r1_w0, const float* __restrict__ r1_b0,
    const float* __restrict__ r1_w1, const float* __restrict__ r1_b1,
    const float* __restrict__ r1_w2, const float* __restrict__ r1_b2,
    const float* __restrict__ r1_w3, const float* __restrict__ r1_b3,
    const float* __restrict__ mix_l0, const float* __restrict__ mix_l1,
    const float* __restrict__ mix_l2)
{
    extern __shared__ float sm[];
    float* Xin = sm;            // 576  ([64][9])
    float* Ysm = Xin + 576;     // 512
    float* mk  = Ysm + 512;     // 64
    float* Wb  = mk + 64;       // 4096
    float* A0  = Wb + 4096;     // 4224 ([64][66])
    float* A1  = A0 + 4224;     // 4224
    float* G   = A1 + 4224;     // 576
    float* S   = G + 576;       // 16
    float* msg = S + 16;        // 1152
    float* t2  = msg + 1152;    // 128  -> 15568 floats (62.3KB)

    int t = threadIdx.x;
    int node = blockIdx.x;
    int pbase = node * 64;

    for (int idx = t; idx < 576; idx += 128) {
        int j = idx / 9, c = idx - j*9;
        Xin[idx] = (c < 8) ? g_rad[(size_t)pbase*8 + j*8 + c] : 0.0f;
    }
    for (int idx = t; idx < 512; idx += 128)
        Ysm[idx] = g_Y[(size_t)pbase*8 + idx] * g_mask[pbase + (idx >> 3)];
    if (t < 64) mk[t] = g_mask[pbase + t];
    for (int idx = t; idx < 512; idx += 128) Wb[idx] = r1_w0[idx];
    __syncthreads();

    dl128<8,9>(Xin, Wb, r1_b0, A0, t);
    __syncthreads();
    for (int idx = t; idx < 4096; idx += 128) Wb[idx] = r1_w1[idx];
    __syncthreads();
    dl128<64,66>(A0, Wb, r1_b1, A1, t);
    __syncthreads();
    for (int idx = t; idx < 4096; idx += 128) Wb[idx] = r1_w2[idx];
    __syncthreads();
    dl128<64,66>(A1, Wb, r1_b2, A0, t);   // final H in A0 (stride 66)
    __syncthreads();

    // G[m][c] = sum_j maskY_m(j) * H[j][c]
    for (int idx = t; idx < 576; idx += 128) {
        int m = idx >> 6, c = idx & 63;
        float acc = 0.0f, accB = 0.0f;
        #pragma unroll 8
        for (int j = 0; j < 64; j += 2) {
            float y0 = (m == 0) ? mk[j]   : Ysm[j*8 + m - 1];
            float y1 = (m == 0) ? mk[j+1] : Ysm[(j+1)*8 + m - 1];
            acc  += y0 * A0[j*66 + c];
            accB += y1 * A0[(j+1)*66 + c];
        }
        G[idx] = acc + accB;
    }
    if (t < 9) {
        float acc = 0.0f;
        for (int j = 0; j < 64; ++j) acc += (t == 0) ? mk[j] : Ysm[j*8 + t - 1];
        S[t] = acc;
    }
    __syncthreads();

    // msg[m][k] = (w_embed[k]/16)*(b3[o]*S[m] + sum_c G[m][c]*W3[c][o])
    {
        int k = t;
        float wk = w_embed[k] * 0.0625f;
        #pragma unroll 1
        for (int m = 0; m < 9; ++m) {
            int o = k + ((m == 0) ? 0 : ((m <= 3) ? 128 : 256));
            float acc = r1_b3[o] * S[m], acc2 = 0.0f;
            const float* Gm = G + m*64;
            #pragma unroll 8
            for (int c = 0; c < 64; c += 2) {
                acc  += Gm[c]   * __ldg(r1_w3 + c*384 + o);
                acc2 += Gm[c+1] * __ldg(r1_w3 + (c+1)*384 + o);
            }
            msg[m*128 + k] = (acc + acc2) * wk;
        }
    }
    __syncthreads();
    {
        float a4 = msg[4*128+t], a5 = msg[5*128+t], a6 = msg[6*128+t],
              a7 = msg[7*128+t], a8 = msg[8*128+t];
        t2[t] = a4*a4 + a5*a5 + a6*a6 + a7*a7 + a8*a8;
    }
    __syncthreads();

    // s1 = msg0@l0 + t2@l2 ; v1[m] = msg1[m]@l1 ; h1 = silu(s1)
    {
        int k = t;
        float s = 0.0f, sB = 0.0f;
        #pragma unroll 4
        for (int c = 0; c < 128; c += 2) {
            s  += msg[c]  *__ldg(mix_l0 + c*128 + k)     + t2[c]  *__ldg(mix_l2 + c*128 + k);
            sB += msg[c+1]*__ldg(mix_l0 + (c+1)*128 + k) + t2[c+1]*__ldg(mix_l2 + (c+1)*128 + k);
        }
        s += sB;
        g_s1[node*128 + k] = s;
        g_h1[node*128 + k] = siluf(s);
        #pragma unroll
        for (int m = 0; m < 3; ++m) {
            float v = 0.0f, vB = 0.0f;
            const float* mm = msg + (m+1)*128;
            #pragma unroll 4
            for (int c = 0; c < 128; c += 2) {
                v  += mm[c]  *__ldg(mix_l1 + c*128 + k);
                vB += mm[c+1]*__ldg(mix_l1 + (c+1)*128 + k);
            }
            g_v1[(node*3 + m)*128 + k] = v + vB;
        }
    }
}

// ---------------- kernel 3: phase 2 (128 threads, k-quartered smem E-GEMM) ----------------
__global__ void __launch_bounds__(128) k_phase2(
    const float* __restrict__ r2_w0, const float* __restrict__ r2_b0,
    const float* __restrict__ r2_w1, const float* __restrict__ r2_b1,
    const float* __restrict__ r2_w2, const float* __restrict__ r2_b2,
    const float* __restrict__ r2_w3, const float* __restrict__ r2_b3,
    const float* __restrict__ mix2)
{
    extern __shared__ float sm[];
    float* Xin = sm;            // 576
    float* mk  = Xin + 576;     // 64
    float* Y1s = mk + 64;       // 192
    float* Wb  = Y1s + 192;     // 4096
    float* A0  = Wb + 4096;     // 4224 (H' stride 66)
    float* A1  = A0 + 4224;     // 4224 (Es overlay: [64][64])
    float* msA = A1 + 4224;     // 128
    float* msB = msA + 128;     // 128
    float* prt = msB + 128;     // 128 -> 13760 floats (55KB)
    float* Es  = A1;

    int t = threadIdx.x;
    int node = blockIdx.x;
    int b = node >> 6;
    int pbase = node * 64;

    for (int idx = t; idx < 576; idx += 128) {
        int j = idx / 9, c = idx - j*9;
        Xin[idx] = (c < 8) ? g_rad[(size_t)pbase*8 + j*8 + c] : 0.0f;
    }
    if (t < 64) mk[t] = g_mask[pbase + t];
    if (t < 128) { msA[t] = 0.0f; msB[t] = 0.0f; }
    for (int idx = t; idx < 192; idx += 128) {
        int j = idx / 3, m = idx - j*3;
        Y1s[idx] = g_Y[(size_t)pbase*8 + j*8 + m] * g_mask[pbase + j];
    }
    for (int idx = t; idx < 512; idx += 128) Wb[idx] = r2_w0[idx];
    __syncthreads();

    dl128<8,9>(Xin, Wb, r2_b0, A0, t);
    __syncthreads();
    for (int idx = t; idx < 4096; idx += 128) Wb[idx] = r2_w1[idx];
    __syncthreads();
    dl128<64,66>(A0, Wb, r2_b1, A1, t);
    __syncthreads();
    for (int idx = t; idx < 4096; idx += 128) Wb[idx] = r2_w2[idx];
    __syncthreads();
    dl128<64,66>(A1, Wb, r2_b2, A0, t);   // final H' in A0 (stride 66)
    __syncthreads();

    // 4 k-quarters of E[j][k] = b3[kq+k] + sum_c H'[j][c]*W3[c][kq+k]
    // quarters 0,1 -> msg_a (p = mask*h1); quarters 2,3 -> msg_b (q = Y1·v1)
    int j0 = (t >> 4) * 8;      // 8 j-rows per thread
    int k0 = (t & 15) * 4;      // 4 k-cols per thread
    int kq_ = t & 63;           // dot: k within quarter
    int jh  = t >> 6;           // dot: j-half

    #pragma unroll 1
    for (int q = 0; q < 4; ++q) {
        int kb = q * 64;
        // stage W3 quarter into Wb: [c][64]
        for (int idx = t; idx < 4096; idx += 128) {
            int c = idx >> 6, k = idx & 63;
            Wb[idx] = r2_w3[c*256 + kb + k];
        }
        __syncthreads();
        // GEMM: 8j x 4k per thread
        {
            float acc[8][4];
            #pragma unroll
            for (int i = 0; i < 4; ++i) {
                float bv = r2_b3[kb + k0 + i];
                #pragma unroll
                for (int r = 0; r < 8; ++r) acc[r][i] = bv;
            }
            #pragma unroll 2
            for (int c = 0; c < 64; ++c) {
                float4 wv = *(const float4*)(Wb + c*64 + k0);
                #pragma unroll
                for (int r = 0; r < 8; ++r) {
                    float h = A0[(j0+r)*66 + c];
                    acc[r][0] += h*wv.x; acc[r][1] += h*wv.y;
                    acc[r][2] += h*wv.z; acc[r][3] += h*wv.w;
                }
            }
            #pragma unroll
            for (int r = 0; r < 8; ++r) {
                float4 st; st.x = acc[r][0]; st.y = acc[r][1]; st.z = acc[r][2]; st.w = acc[r][3];
                *(float4*)(Es + (j0+r)*64 + k0) = st;
            }
        }
        __syncthreads();
        // dot over j-half
        {
            int jlo = jh * 32;
            float s = 0.0f, sB = 0.0f;
            if (q < 2) {
                const float* h1p = g_h1 + (b*64 + jlo)*128 + kb + kq_;
                #pragma unroll 8
                for (int j = jlo; j < jlo + 32; j += 2) {
                    float p0 = mk[j]   * __ldg(h1p);
                    float p1 = mk[j+1] * __ldg(h1p + 128);
                    s  += p0 * Es[j*64 + kq_];
                    sB += p1 * Es[(j+1)*64 + kq_];
                    h1p += 256;
                }
            } else {
                const float* vp = g_v1 + ((size_t)(b*64 + jlo)*3)*128 + (kb - 128) + kq_;
                #pragma unroll 8
                for (int j = jlo; j < jlo + 32; ++j) {
                    float q0 = Y1s[j*3+0]*__ldg(vp) + Y1s[j*3+1]*__ldg(vp+128)
                             + Y1s[j*3+2]*__ldg(vp+256);
                    s += q0 * Es[j*64 + kq_];
                    vp += 384;
                }
            }
            prt[t] = s + sB;
        }
        __syncthreads();
        if (t < 64) {
            float v = prt[t] + prt[64 + t];
            if (q < 2) msA[kb + t] = v;
            else       msB[(kb - 128) + t] = v;
        }
        __syncthreads();
    }

    // msS = (msA + msB)/16 ; s2 = msS @ mix2
    if (t < 128) msA[t] = (msA[t] + msB[t]) * 0.0625f;
    __syncthreads();
    {
        float s = 0.0f, sB = 0.0f;
        #pragma unroll 4
        for (int c = 0; c < 128; c += 2) {
            s  += msA[c]  *__ldg(mix2 + c*128 + t);
            sB += msA[c+1]*__ldg(mix2 + (c+1)*128 + t);
        }
        g_s2[node*128 + t] = s + sB;
    }
}

// ---------------- kernel 4: final MLP (8 nodes/block, transposed, FFMA2) ----------------
__global__ void __launch_bounds__(512) k_mlp(
    const float* __restrict__ tim,
    const float* __restrict__ w0, const float* __restrict__ b0,
    const float* __restrict__ w1, const float* __restrict__ b1,
    const float* __restrict__ w2, const float* __restrict__ b2,
    float* __restrict__ out)
{
    extern __shared__ float sm[];
    float* xs_t  = sm;              // [641][8] = 5128
    float* h0s_t = xs_t + 5128;     // [512][8] = 4096
    float* h1s_t = xs_t;

    int t = threadIdx.x;
    int rbase = blockIdx.x * 8;

    for (int idx = t; idx < 8*641; idx += 512) {
        int c = idx >> 3, r = idx & 7;
        int node = rbase + r;
        float v;
        if (c < 128)       v = g_s1[node*128 + c];
        else if (c < 512)  v = g_v1[(size_t)node*384 + (c - 128)];
        else if (c < 640)  v = g_s2[node*128 + (c - 512)];
        else               v = tim[node >> 6];
        xs_t[c*8 + r] = v;
    }
    __syncthreads();

    {
        u64 acc[4];
        u64 bb = pk2(b0[t], b0[t]);
        #pragma unroll
        for (int i = 0; i < 4; ++i) acc[i] = bb;
        #pragma unroll 4
        for (int c = 0; c < 641; ++c) {
            float w = __ldg(w0 + c*512 + t);
            u64 wp = pk2(w, w);
            const longlong2* xp = (const longlong2*)(xs_t + c*8);
            longlong2 qa = xp[0], qb = xp[1];
            fma2(acc[0], (u64)qa.x, wp); fma2(acc[1], (u64)qa.y, wp);
            fma2(acc[2], (u64)qb.x, wp); fma2(acc[3], (u64)qb.y, wp);
        }
        #pragma unroll
        for (int i = 0; i < 4; ++i) {
            float2 p = upk(acc[i]);
            h0s_t[t*8 + 2*i]     = fmaxf(p.x, 0.0f);
            h0s_t[t*8 + 2*i + 1] = fmaxf(p.y, 0.0f);
        }
    }
    __syncthreads();

    {
        u64 acc[4];
        u64 bb = pk2(b1[t], b1[t]);
        #pragma unroll
        for (int i = 0; i < 4; ++i) acc[i] = bb;
        #pragma unroll 4
        for (int c = 0; c < 512; ++c) {
            float w = __ldg(w1 + c*512 + t);
            u64 wp = pk2(w, w);
            const longlong2* xp = (const longlong2*)(h0s_t + c*8);
            longlong2 qa = xp[0], qb = xp[1];
            fma2(acc[0], (u64)qa.x, wp); fma2(acc[1], (u64)qa.y, wp);
            fma2(acc[2], (u64)qb.x, wp); fma2(acc[3], (u64)qb.y, wp);
        }
        #pragma unroll
        for (int i = 0; i < 4; ++i) {
            float2 p = upk(acc[i]);
            h1s_t[t*8 + 2*i]     = fmaxf(p.x, 0.0f);
            h1s_t[t*8 + 2*i + 1] = fmaxf(p.y, 0.0f);
        }
    }
    __syncthreads();

    {
        int wid = t >> 5, lane = t & 31;
        if (wid < 8) {
            int r = wid;
            float p0 = 0.0f, p1 = 0.0f, p2 = 0.0f;
            for (int c = lane; c < 512; c += 32) {
                float hv = h1s_t[c*8 + r];
                p0 += hv * w2[c*3 + 0];
                p1 += hv * w2[c*3 + 1];
                p2 += hv * w2[c*3 + 2];
            }
            #pragma unroll
            for (int off = 16; off > 0; off >>= 1) {
                p0 += __shfl_down_sync(0xffffffffu, p0, off);
                p1 += __shfl_down_sync(0xffffffffu, p1, off);
                p2 += __shfl_down_sync(0xffffffffu, p2, off);
            }
            if (lane == 0) {
                int node = rbase + r;
                out[node*3 + 0] = p0 + b2[0];
                out[node*3 + 1] = p1 + b2[1];
                out[node*3 + 2] = p2 + b2[2];
            }
        }
    }
}

// ---------------- launch ----------------
extern "C" void kernel_launch(void* const* d_in, const int* in_sizes, int n_in,
                              void* d_out, int out_size)
{
    const float* frac    = (const float*)d_in[0];
    const float* tim     = (const float*)d_in[1];
    const float* cell    = (const float*)d_in[2];
    const float* w_embed = (const float*)d_in[3];
    const float* r1_w0 = (const float*)d_in[4];
    const float* r1_b0 = (const float*)d_in[5];
    const float* r1_w1 = (const float*)d_in[6];
    const float* r1_b1 = (const float*)d_in[7];
    const float* r1_w2 = (const float*)d_in[8];
    const float* r1_b2 = (const float*)d_in[9];
    const float* r1_w3 = (const float*)d_in[10];
    const float* r1_b3 = (const float*)d_in[11];
    const float* mix1_l0 = (const float*)d_in[12];
    const float* mix1_l1 = (const float*)d_in[13];
    const float* mix1_l2 = (const float*)d_in[14];
    const float* r2_w0 = (const float*)d_in[15];
    const float* r2_b0 = (const float*)d_in[16];
    const float* r2_w1 = (const float*)d_in[17];
    const float* r2_b1 = (const float*)d_in[18];
    const float* r2_w2 = (const float*)d_in[19];
    const float* r2_b2 = (const float*)d_in[20];
    const float* r2_w3 = (const float*)d_in[21];
    const float* r2_b3 = (const float*)d_in[22];
    const float* mix2  = (const float*)d_in[23];
    const float* mlp_w0 = (const float*)d_in[24];
    const float* mlp_b0 = (const float*)d_in[25];
    const float* mlp_w1 = (const float*)d_in[26];
    const float* mlp_b1 = (const float*)d_in[27];
    const float* mlp_w2 = (const float*)d_in[28];
    const float* mlp_b2 = (const float*)d_in[29];

    const int SM_P1  = 15568 * 4;
    const int SM_P2  = 13760 * 4;
    const int SM_MLP = (5128 + 4096) * 4;

    cudaFuncSetAttribute(k_phase1, cudaFuncAttributeMaxDynamicSharedMemorySize, SM_P1);
    cudaFuncSetAttribute(k_phase2, cudaFuncAttributeMaxDynamicSharedMemorySize, SM_P2);
    cudaFuncSetAttribute(k_mlp,    cudaFuncAttributeMaxDynamicSharedMemorySize, SM_MLP);

    k_geom<<<NPAIR/256, 256>>>(frac, cell);
    k_phase1<<<NNODE, 128, SM_P1>>>(w_embed,
        r1_w0, r1_b0, r1_w1, r1_b1, r1_w2, r1_b2, r1_w3, r1_b3,
        mix1_l0, mix1_l1, mix1_l2);
    k_phase2<<<NNODE, 128, SM_P2>>>(
        r2_w0, r2_b0, r2_w1, r2_b1, r2_w2, r2_b2, r2_w3, r2_b3, mix2);
    k_mlp<<<NNODE/8, 512, SM_MLP>>>(tim, mlp_w0, mlp_b0, mlp_w1, mlp_b1,
        mlp_w2, mlp_b2, (float*)d_out);
}

// round 10
// speedup vs baseline: 1.6664x; 1.6664x over previous
#include <cuda_runtime.h>
#include <math.h>

#define BB 32
#define NN 64
#define KK 128
#define NPAIR (BB*NN*NN)   // 131072
#define NNODE (BB*NN)      // 2048

// ---------------- scratch (no cudaMalloc allowed) ----------------
__device__ float g_rad[NPAIR*8];
__device__ float g_Y[NPAIR*8];
__device__ float g_mask[NPAIR];
__device__ float g_h1[NNODE*KK];
__device__ float g_s1[NNODE*KK];
__device__ float g_v1[NNODE*3*KK];
__device__ float g_s2[NNODE*KK];

__device__ __forceinline__ float siluf(float x) { return x / (1.0f + __expf(-x)); }

typedef unsigned long long u64;
__device__ __forceinline__ u64 pk2(float lo, float hi) {
    u64 r; asm("mov.b64 %0, {%1,%2};" : "=l"(r) : "f"(lo), "f"(hi)); return r;
}
__device__ __forceinline__ void fma2(u64& a, u64 x, u64 y) {
    asm("fma.rn.f32x2 %0, %1, %2, %3;" : "=l"(a) : "l"(x), "l"(y), "l"(a));
}
__device__ __forceinline__ float2 upk(u64 v) {
    float2 o; asm("mov.b64 {%0,%1}, %2;" : "=f"(o.x), "=f"(o.y) : "l"(v)); return o;
}

// ---------------- kernel 1: pairwise geometry ----------------
__global__ void k_geom(const float* __restrict__ frac, const float* __restrict__ cell)
{
    int idx = blockIdx.x * blockDim.x + threadIdx.x;
    if (idx >= NPAIR) return;
    int b = idx >> 12;
    int i = (idx >> 6) & 63;
    int j = idx & 63;
    const float* fi = frac + (b*NN + i)*3;
    const float* fj = frac + (b*NN + j)*3;
    float d0 = fi[0]-fj[0], d1 = fi[1]-fj[1], d2 = fi[2]-fj[2];
    d0 -= rintf(d0); d1 -= rintf(d1); d2 -= rintf(d2);
    const float* C = cell + b*9;
    float x = d0*C[0] + d1*C[3] + d2*C[6];
    float y = d0*C[1] + d1*C[4] + d2*C[7];
    float z = d0*C[2] + d1*C[5] + d2*C[8];
    float r2 = fmaxf(x*x + y*y + z*z, 1e-12f);
    float r = sqrtf(r2);
    bool m = (r < 5.0f) && (i != j);
    float mf = m ? 1.0f : 0.0f;
    float rs = m ? r : 1.0f;
    float inv = 1.0f / rs;
    float ux = x*inv*mf, uy = y*inv*mf, uz = z*inv*mf;
    float u = rs * 0.2f;
    float u2 = u*u, u4 = u2*u2, u5 = u4*u;
    float fc = 1.0f - 21.0f*u5 + 35.0f*u5*u - 15.0f*u5*u2;
    fc = (u < 1.0f) ? fc : 0.0f;
    float pref = 0.6324555320336759f * inv * fc * mf;
    float w = 0.6283185307179586f * rs;
    float* rp = g_rad + (size_t)idx*8;
    #pragma unroll
    for (int n = 1; n <= 8; ++n) rp[n-1] = pref * sinf((float)n * w);
    const float s3 = 1.7320508075688772f, s5 = 2.23606797749979f, s15 = 3.872983346207417f;
    float* Y = g_Y + (size_t)idx*8;
    Y[0] = s3*ux; Y[1] = s3*uy; Y[2] = s3*uz;
    Y[3] = s15*ux*uy;
    Y[4] = s15*uy*uz;
    Y[5] = 0.5f*s5*(3.0f*uz*uz - 1.0f);
    Y[6] = s15*ux*uz;
    Y[7] = 0.5f*s15*(ux*ux - uy*uy);
    g_mask[idx] = mf;
}

// ---------------- shared 64-wide dense layer (silu), R3-proven form ----------------
// In: [64][ldi] smem, Wsh: [CDIM][64] smem, Out: [64][64] smem.  128 threads.
template<int CDIM>
__device__ __forceinline__ void dense_layer(const float* __restrict__ In, int ldi,
                                            const float* __restrict__ Wsh,
                                            const float* __restrict__ bias,
                                            float* __restrict__ Out, int t)
{
    #pragma unroll 1
    for (int it = 0; it < 8; ++it) {
        int j  = (t >> 4) + 8*it;
        int h0 = (t & 15) * 4;
        float a0 = bias[h0+0], a1 = bias[h0+1], a2 = bias[h0+2], a3 = bias[h0+3];
        const float* inj = In + j*ldi;
        #pragma unroll 4
        for (int c = 0; c < CDIM; ++c) {
            float av = inj[c];
            float4 wv = *(const float4*)(Wsh + c*64 + h0);
            a0 += av*wv.x; a1 += av*wv.y; a2 += av*wv.z; a3 += av*wv.w;
        }
        float4 o4;
        o4.x = siluf(a0); o4.y = siluf(a1); o4.z = siluf(a2); o4.w = siluf(a3);
        *(float4*)(Out + j*64 + h0) = o4;
    }
}

// ---------------- kernel 2: phase 1 (128 threads, R3 + overlay + LDG dedup) ----------------
__global__ void __launch_bounds__(128) k_phase1(
    const float* __restrict__ w_embed,
    const float* __restrict__ r1_w0, const float* __restrict__ r1_b0,
    const float* __restrict__ r1_w1, const float* __restrict__ r1_b1,
    const float* __restrict__ r1_w2, const float* __restrict__ r1_b2,
    const float* __restrict__ r1_w3, const float* __restrict__ r1_b3,
    const float* __restrict__ mix_l0, const float* __restrict__ mix_l1,
    const float* __restrict__ mix_l2)
{
    extern __shared__ float sm[];
    float* Xin = sm;            // 512
    float* Ysm = Xin + 512;     // 512 (mask premultiplied)
    float* mk  = Ysm + 512;     // 64
    float* Ha  = mk + 64;       // 4096
    float* Hb  = Ha + 4096;     // 4096 (overlaid by G/S/msg/t2 after L3)
    float* Wb  = Hb + 4096;     // 4096  -> total 13376 floats (53.5KB)
    // overlays inside Hb (free after layer 3):
    float* G   = Hb;            // 576
    float* S   = Hb + 576;      // 16
    float* msg = Hb + 592;      // 1152
    float* t2  = Hb + 1744;     // 128

    int t = threadIdx.x;
    int node = blockIdx.x;
    int pbase = node * 64;

    for (int idx = t; idx < 512; idx += 128) Xin[idx] = g_rad[(size_t)pbase*8 + idx];
    for (int idx = t; idx < 512; idx += 128)
        Ysm[idx] = g_Y[(size_t)pbase*8 + idx] * g_mask[pbase + (idx >> 3)];
    if (t < 64) mk[t] = g_mask[pbase + t];
    for (int idx = t; idx < 512; idx += 128) Wb[idx] = r1_w0[idx];
    __syncthreads();

    dense_layer<8>(Xin, 8, Wb, r1_b0, Ha, t);
    __syncthreads();
    for (int idx = t; idx < 4096; idx += 128) Wb[idx] = r1_w1[idx];
    __syncthreads();
    dense_layer<64>(Ha, 64, Wb, r1_b1, Hb, t);
    __syncthreads();
    for (int idx = t; idx < 4096; idx += 128) Wb[idx] = r1_w2[idx];
    __syncthreads();
    dense_layer<64>(Hb, 64, Wb, r1_b2, Ha, t);   // final H in Ha; Hb now free
    __syncthreads();

    // G[m][c] = sum_j maskY_m(j) * H[j][c]  (G overlays Hb)
    for (int idx = t; idx < 576; idx += 128) {
        int m = idx >> 6, c = idx & 63;
        float acc = 0.0f;
        #pragma unroll 8
        for (int j = 0; j < 64; ++j) {
            float yv = (m == 0) ? mk[j] : Ysm[j*8 + m - 1];
            acc += yv * Ha[j*64 + c];
        }
        G[idx] = acc;
    }
    if (t < 9) {
        float acc = 0.0f;
        for (int j = 0; j < 64; ++j) acc += (t == 0) ? mk[j] : Ysm[j*8 + t - 1];
        S[t] = acc;
    }
    __syncthreads();

    // msg[m][k]: m=0 uses W3 col k; m=1..3 share col 128+k; m=4..8 share col 256+k.
    // One pass over c with 3 LDG per c feeding 9 accumulators.
    {
        int k = t;
        float wk = w_embed[k] * 0.0625f;
        float acc[9];
        float b3_0 = r1_b3[k], b3_1 = r1_b3[128 + k], b3_2 = r1_b3[256 + k];
        acc[0] = b3_0 * S[0];
        #pragma unroll
        for (int m = 1; m <= 3; ++m) acc[m] = b3_1 * S[m];
        #pragma unroll
        for (int m = 4; m <= 8; ++m) acc[m] = b3_2 * S[m];
        const float* w3p = r1_w3 + k;
        #pragma unroll 4
        for (int c = 0; c < 64; ++c) {
            float w0 = __ldg(w3p + c*384);
            float w1 = __ldg(w3p + c*384 + 128);
            float w2 = __ldg(w3p + c*384 + 256);
            acc[0] += G[c] * w0;
            acc[1] += G[64 + c]  * w1;
            acc[2] += G[128 + c] * w1;
            acc[3] += G[192 + c] * w1;
            acc[4] += G[256 + c] * w2;
            acc[5] += G[320 + c] * w2;
            acc[6] += G[384 + c] * w2;
            acc[7] += G[448 + c] * w2;
            acc[8] += G[512 + c] * w2;
        }
        #pragma unroll
        for (int m = 0; m < 9; ++m) msg[m*128 + k] = acc[m] * wk;
    }
    __syncthreads();
    {
        float a4 = msg[4*128+t], a5 = msg[5*128+t], a6 = msg[6*128+t],
              a7 = msg[7*128+t], a8 = msg[8*128+t];
        t2[t] = a4*a4 + a5*a5 + a6*a6 + a7*a7 + a8*a8;
    }
    __syncthreads();

    // fused: s1 = msg0@l0 + t2@l2 ; v1[m] = msg1[m]@l1 (one l1 load feeds 3 FMA)
    {
        int k = t;
        float s = 0.0f, v0 = 0.0f, v1 = 0.0f, v2 = 0.0f;
        const float* l0p = mix_l0 + k;
        const float* l1p = mix_l1 + k;
        const float* l2p = mix_l2 + k;
        #pragma unroll 4
        for (int c = 0; c < 128; ++c) {
            float w0 = __ldg(l0p + c*128);
            float w1 = __ldg(l1p + c*128);
            float w2 = __ldg(l2p + c*128);
            s  += msg[c]*w0 + t2[c]*w2;
            v0 += msg[128 + c]*w1;
            v1 += msg[256 + c]*w1;
            v2 += msg[384 + c]*w1;
        }
        g_s1[node*128 + k] = s;
        g_h1[node*128 + k] = siluf(s);
        g_v1[(node*3 + 0)*128 + k] = v0;
        g_v1[(node*3 + 1)*128 + k] = v1;
        g_v1[(node*3 + 2)*128 + k] = v2;
    }
}

// ---------------- kernel 3: phase 2 (128 threads, R3-proven form) ----------------
__global__ void __launch_bounds__(128) k_phase2(
    const float* __restrict__ r2_w0, const float* __restrict__ r2_b0,
    const float* __restrict__ r2_w1, const float* __restrict__ r2_b1,
    const float* __restrict__ r2_w2, const float* __restrict__ r2_b2,
    const float* __restrict__ r2_w3, const float* __restrict__ r2_b3,
    const float* __restrict__ mix2)
{
    extern __shared__ float sm[];
    float* Xin  = sm;            // 512
    float* mk   = Xin + 512;     // 64
    float* Y1s  = mk + 64;       // 192
    float* Ha   = Y1s + 192;     // 4096
    float* Hb   = Ha + 4096;     // 4096
    float* Wb   = Hb + 4096;     // 4096
    float* msgS = Wb + 4096;     // 128  -> 13184 floats (52.7KB)

    int t = threadIdx.x;
    int node = blockIdx.x;
    int b = node >> 6;
    int pbase = node * 64;

    for (int idx = t; idx < 512; idx += 128) Xin[idx] = g_rad[(size_t)pbase*8 + idx];
    if (t < 64) mk[t] = g_mask[pbase + t];
    for (int idx = t; idx < 192; idx += 128) {
        int j = idx / 3, m = idx - j*3;
        Y1s[idx] = g_Y[(size_t)pbase*8 + j*8 + m] * g_mask[pbase + j];
    }
    for (int idx = t; idx < 512; idx += 128) Wb[idx] = r2_w0[idx];
    __syncthreads();

    dense_layer<8>(Xin, 8, Wb, r2_b0, Ha, t);
    __syncthreads();
    for (int idx = t; idx < 4096; idx += 128) Wb[idx] = r2_w1[idx];
    __syncthreads();
    dense_layer<64>(Ha, 64, Wb, r2_b1, Hb, t);
    __syncthreads();
    for (int idx = t; idx < 4096; idx += 128) Wb[idx] = r2_w2[idx];
    __syncthreads();
    dense_layer<64>(Hb, 64, Wb, r2_b2, Ha, t);   // final H' in Ha
    __syncthreads();

    int k = t;
    float P[64];
    float acc_a, acc_b;
    // msg_a: sum_j mask*we2_0[j,k]*h1[j,k], fused through layer 3
    {
        float sp = 0.0f;
        #pragma unroll
        for (int j = 0; j < 64; ++j) {
            float p = mk[j] * __ldg(g_h1 + (b*64 + j)*128 + k);
            P[j] = p; sp += p;
        }
        float acc = r2_b3[k] * sp;
        #pragma unroll 1
        for (int c = 0; c < 64; c += 4) {
            float s0 = 0.0f, s1 = 0.0f, s2 = 0.0f, s3 = 0.0f;
            #pragma unroll
            for (int j = 0; j < 64; ++j) {
                float4 hv = *(const float4*)(Ha + j*64 + c);
                float pj = P[j];
                s0 += pj*hv.x; s1 += pj*hv.y; s2 += pj*hv.z; s3 += pj*hv.w;
            }
            acc += s0*__ldg(r2_w3 + (c+0)*256 + k) + s1*__ldg(r2_w3 + (c+1)*256 + k)
                 + s2*__ldg(r2_w3 + (c+2)*256 + k) + s3*__ldg(r2_w3 + (c+3)*256 + k);
        }
        acc_a = acc;
    }
    // msg_b: inv[j,k] = sum_m Y1[j,m]*v1[j,m,k] (mask folded into Y1s)
    {
        float sq = 0.0f;
        #pragma unroll
        for (int j = 0; j < 64; ++j) {
            const float* vp = g_v1 + ((size_t)(b*64 + j)*3)*128 + k;
            float q = Y1s[j*3+0]*__ldg(vp) + Y1s[j*3+1]*__ldg(vp+128) + Y1s[j*3+2]*__ldg(vp+256);
            P[j] = q; sq += q;
        }
        float acc = r2_b3[128 + k] * sq;
        #pragma unroll 1
        for (int c = 0; c < 64; c += 4) {
            float s0 = 0.0f, s1 = 0.0f, s2 = 0.0f, s3 = 0.0f;
            #pragma unroll
            for (int j = 0; j < 64; ++j) {
                float4 hv = *(const float4*)(Ha + j*64 + c);
                float pj = P[j];
                s0 += pj*hv.x; s1 += pj*hv.y; s2 += pj*hv.z; s3 += pj*hv.w;
            }
            acc += s0*__ldg(r2_w3 + (c+0)*256 + 128 + k) + s1*__ldg(r2_w3 + (c+1)*256 + 128 + k)
                 + s2*__ldg(r2_w3 + (c+2)*256 + 128 + k) + s3*__ldg(r2_w3 + (c+3)*256 + 128 + k);
        }
        acc_b = acc;
    }
    msgS[k] = (acc_a + acc_b) * 0.0625f;
    __syncthreads();
    {
        float s2v = 0.0f;
        #pragma unroll 4
        for (int c = 0; c < 128; ++c) s2v += msgS[c] * __ldg(mix2 + c*128 + k);
        g_s2[node*128 + k] = s2v;
    }
}

// ---------------- kernel 4: final MLP (8 nodes/block, transposed, FFMA2) ----------------
__global__ void __launch_bounds__(512) k_mlp(
    const float* __restrict__ tim,
    const float* __restrict__ w0, const float* __restrict__ b0,
    const float* __restrict__ w1, const float* __restrict__ b1,
    const float* __restrict__ w2, const float* __restrict__ b2,
    float* __restrict__ out)
{
    extern __shared__ float sm[];
    float* xs_t  = sm;              // [641][8] = 5128
    float* h0s_t = xs_t + 5128;     // [512][8] = 4096
    float* h1s_t = xs_t;

    int t = threadIdx.x;
    int rbase = blockIdx.x * 8;

    for (int idx = t; idx < 8*641; idx += 512) {
        int c = idx >> 3, r = idx & 7;
        int node = rbase + r;
        float v;
        if (c < 128)       v = g_s1[node*128 + c];
        else if (c < 512)  v = g_v1[(size_t)node*384 + (c - 128)];
        else if (c < 640)  v = g_s2[node*128 + (c - 512)];
        else               v = tim[node >> 6];
        xs_t[c*8 + r] = v;
    }
    __syncthreads();

    {
        u64 acc[4];
        u64 bb = pk2(b0[t], b0[t]);
        #pragma unroll
        for (int i = 0; i < 4; ++i) acc[i] = bb;
        #pragma unroll 8
        for (int c = 0; c < 641; ++c) {
            float w = __ldg(w0 + c*512 + t);
            u64 wp = pk2(w, w);
            const longlong2* xp = (const longlong2*)(xs_t + c*8);
            longlong2 qa = xp[0], qb = xp[1];
            fma2(acc[0], (u64)qa.x, wp); fma2(acc[1], (u64)qa.y, wp);
            fma2(acc[2], (u64)qb.x, wp); fma2(acc[3], (u64)qb.y, wp);
        }
        #pragma unroll
        for (int i = 0; i < 4; ++i) {
            float2 p = upk(acc[i]);
            h0s_t[t*8 + 2*i]     = fmaxf(p.x, 0.0f);
            h0s_t[t*8 + 2*i + 1] = fmaxf(p.y, 0.0f);
        }
    }
    __syncthreads();

    {
        u64 acc[4];
        u64 bb = pk2(b1[t], b1[t]);
        #pragma unroll
        for (int i = 0; i < 4; ++i) acc[i] = bb;
        #pragma unroll 8
        for (int c = 0; c < 512; ++c) {
            float w = __ldg(w1 + c*512 + t);
            u64 wp = pk2(w, w);
            const longlong2* xp = (const longlong2*)(h0s_t + c*8);
            longlong2 qa = xp[0], qb = xp[1];
            fma2(acc[0], (u64)qa.x, wp); fma2(acc[1], (u64)qa.y, wp);
            fma2(acc[2], (u64)qb.x, wp); fma2(acc[3], (u64)qb.y, wp);
        }
        #pragma unroll
        for (int i = 0; i < 4; ++i) {
            float2 p = upk(acc[i]);
            h1s_t[t*8 + 2*i]     = fmaxf(p.x, 0.0f);
            h1s_t[t*8 + 2*i + 1] = fmaxf(p.y, 0.0f);
        }
    }
    __syncthreads();

    {
        int wid = t >> 5, lane = t & 31;
        if (wid < 8) {
            int r = wid;
            float p0 = 0.0f, p1 = 0.0f, p2 = 0.0f;
            for (int c = lane; c < 512; c += 32) {
                float hv = h1s_t[c*8 + r];
                p0 += hv * w2[c*3 + 0];
                p1 += hv * w2[c*3 + 1];
                p2 += hv * w2[c*3 + 2];
            }
            #pragma unroll
            for (int off = 16; off > 0; off >>= 1) {
                p0 += __shfl_down_sync(0xffffffffu, p0, off);
                p1 += __shfl_down_sync(0xffffffffu, p1, off);
                p2 += __shfl_down_sync(0xffffffffu, p2, off);
            }
            if (lane == 0) {
                int node = rbase + r;
                out[node*3 + 0] = p0 + b2[0];
                out[node*3 + 1] = p1 + b2[1];
                out[node*3 + 2] = p2 + b2[2];
            }
        }
    }
}

// ---------------- launch ----------------
extern "C" void kernel_launch(void* const* d_in, const int* in_sizes, int n_in,
                              void* d_out, int out_size)
{
    const float* frac    = (const float*)d_in[0];
    const float* tim     = (const float*)d_in[1];
    const float* cell    = (const float*)d_in[2];
    const float* w_embed = (const float*)d_in[3];
    const float* r1_w0 = (const float*)d_in[4];
    const float* r1_b0 = (const float*)d_in[5];
    const float* r1_w1 = (const float*)d_in[6];
    const float* r1_b1 = (const float*)d_in[7];
    const float* r1_w2 = (const float*)d_in[8];
    const float* r1_b2 = (const float*)d_in[9];
    const float* r1_w3 = (const float*)d_in[10];
    const float* r1_b3 = (const float*)d_in[11];
    const float* mix1_l0 = (const float*)d_in[12];
    const float* mix1_l1 = (const float*)d_in[13];
    const float* mix1_l2 = (const float*)d_in[14];
    const float* r2_w0 = (const float*)d_in[15];
    const float* r2_b0 = (const float*)d_in[16];
    const float* r2_w1 = (const float*)d_in[17];
    const float* r2_b1 = (const float*)d_in[18];
    const float* r2_w2 = (const float*)d_in[19];
    const float* r2_b2 = (const float*)d_in[20];
    const float* r2_w3 = (const float*)d_in[21];
    const float* r2_b3 = (const float*)d_in[22];
    const float* mix2  = (const float*)d_in[23];
    const float* mlp_w0 = (const float*)d_in[24];
    const float* mlp_b0 = (const float*)d_in[25];
    const float* mlp_w1 = (const float*)d_in[26];
    const float* mlp_b1 = (const float*)d_in[27];
    const float* mlp_w2 = (const float*)d_in[28];
    const float* mlp_b2 = (const float*)d_in[29];

    const int SM_P1  = 13376 * 4;
    const int SM_P2  = 13184 * 4;
    const int SM_MLP = (5128 + 4096) * 4;

    cudaFuncSetAttribute(k_phase1, cudaFuncAttributeMaxDynamicSharedMemorySize, SM_P1);
    cudaFuncSetAttribute(k_phase2, cudaFuncAttributeMaxDynamicSharedMemorySize, SM_P2);
    cudaFuncSetAttribute(k_mlp,    cudaFuncAttributeMaxDynamicSharedMemorySize, SM_MLP);
    cudaFuncSetAttribute(k_phase1, cudaFuncAttributePreferredSharedMemoryCarveout, 100);
    cudaFuncSetAttribute(k_phase2, cudaFuncAttributePreferredSharedMemoryCarveout, 100);

    k_geom<<<NPAIR/256, 256>>>(frac, cell);
    k_phase1<<<NNODE, 128, SM_P1>>>(w_embed,
        r1_w0, r1_b0, r1_w1, r1_b1, r1_w2, r1_b2, r1_w3, r1_b3,
        mix1_l0, mix1_l1, mix1_l2);
    k_phase2<<<NNODE, 128, SM_P2>>>(
        r2_w0, r2_b0, r2_w1, r2_b1, r2_w2, r2_b2, r2_w3, r2_b3, mix2);
    k_mlp<<<NNODE/8, 512, SM_MLP>>>(tim, mlp_w0, mlp_b0, mlp_w1, mlp_b1,
        mlp_w2, mlp_b2, (float*)d_out);
}

// round 11
// speedup vs baseline: 1.9756x; 1.1856x over previous
#include <cuda_runtime.h>
#include <math.h>

#define BB 32
#define NN 64
#define KK 128
#define NPAIR (BB*NN*NN)
#define NNODE (BB*NN)

__device__ float g_rad[NPAIR*8];
__device__ float g_Y[NPAIR*8];
__device__ float g_mask[NPAIR];
__device__ float g_h1[NNODE*KK];
__device__ float g_s1[NNODE*KK];
__device__ float g_v1[NNODE*3*KK];
__device__ float g_s2[NNODE*KK];

__device__ __forceinline__ float siluf(float x) { return x / (1.0f + __expf(-x)); }

typedef unsigned long long u64;
__device__ __forceinline__ u64 pk2(float lo, float hi) {
    u64 r; asm("mov.b64 %0, {%1,%2};" : "=l"(r) : "f"(lo), "f"(hi)); return r;
}
__device__ __forceinline__ void fma2(u64& a, u64 x, u64 y) {
    asm("fma.rn.f32x2 %0, %1, %2, %3;" : "=l"(a) : "l"(x), "l"(y), "l"(a));
}
__device__ __forceinline__ float2 upk(u64 v) {
    float2 o; asm("mov.b64 {%0,%1}, %2;" : "=f"(o.x), "=f"(o.y) : "l"(v)); return o;
}

// ---------------- kernel 1: pairwise geometry ----------------
__global__ void k_geom(const float* __restrict__ frac, const float* __restrict__ cell)
{
    int idx = blockIdx.x * blockDim.x + threadIdx.x;
    if (idx >= NPAIR) return;
    int b = idx >> 12;
    int i = (idx >> 6) & 63;
    int j = idx & 63;
    const float* fi = frac + (b*NN + i)*3;
    const float* fj = frac + (b*NN + j)*3;
    float d0 = fi[0]-fj[0], d1 = fi[1]-fj[1], d2 = fi[2]-fj[2];
    d0 -= rintf(d0); d1 -= rintf(d1); d2 -= rintf(d2);
    const float* C = cell + b*9;
    float x = d0*C[0] + d1*C[3] + d2*C[6];
    float y = d0*C[1] + d1*C[4] + d2*C[7];
    float z = d0*C[2] + d1*C[5] + d2*C[8];
    float r2 = fmaxf(x*x + y*y + z*z, 1e-12f);
    float r = sqrtf(r2);
    bool m = (r < 5.0f) && (i != j);
    float mf = m ? 1.0f : 0.0f;
    float rs = m ? r : 1.0f;
    float inv = 1.0f / rs;
    float ux = x*inv*mf, uy = y*inv*mf, uz = z*inv*mf;
    float u = rs * 0.2f;
    float u2 = u*u, u4 = u2*u2, u5 = u4*u;
    float fc = 1.0f - 21.0f*u5 + 35.0f*u5*u - 15.0f*u5*u2;
    fc = (u < 1.0f) ? fc : 0.0f;
    float pref = 0.6324555320336759f * inv * fc * mf;
    float w = 0.6283185307179586f * rs;
    float* rp = g_rad + (size_t)idx*8;
    #pragma unroll
    for (int n = 1; n <= 8; ++n) rp[n-1] = pref * sinf((float)n * w);
    const float s3 = 1.7320508075688772f, s5 = 2.23606797749979f, s15 = 3.872983346207417f;
    float* Y = g_Y + (size_t)idx*8;
    Y[0] = s3*ux; Y[1] = s3*uy; Y[2] = s3*uz;
    Y[3] = s15*ux*uy;
    Y[4] = s15*uy*uz;
    Y[5] = 0.5f*s5*(3.0f*uz*uz - 1.0f);
    Y[6] = s15*ux*uz;
    Y[7] = 0.5f*s15*(ux*ux - uy*uy);
    g_mask[idx] = mf;
}

// ---------------- 64-wide dense layer (silu), 2 j-rows per thread ----------------
// In: [64][ldi] smem, Wsh: [CDIM][64] smem, Out: [64][64] smem.  128 threads.
template<int CDIM>
__device__ __forceinline__ void dense_layer(const float* __restrict__ In, int ldi,
                                            const float* __restrict__ Wsh,
                                            const float* __restrict__ bias,
                                            float* __restrict__ Out, int t)
{
    int jbase = t >> 4;
    int h0 = (t & 15) * 4;
    #pragma unroll 1
    for (int it = 0; it < 4; ++it) {
        int jA = jbase + 8*it;
        int jB = jA + 32;
        float a0 = bias[h0+0], a1 = bias[h0+1], a2 = bias[h0+2], a3 = bias[h0+3];
        float b0 = a0, b1 = a1, b2 = a2, b3 = a3;
        const float* inA = In + jA*ldi;
        const float* inB = In + jB*ldi;
        #pragma unroll 4
        for (int c = 0; c < CDIM; ++c) {
            float av = inA[c];
            float bv = inB[c];
            float4 wv = *(const float4*)(Wsh + c*64 + h0);
            a0 += av*wv.x; a1 += av*wv.y; a2 += av*wv.z; a3 += av*wv.w;
            b0 += bv*wv.x; b1 += bv*wv.y; b2 += bv*wv.z; b3 += bv*wv.w;
        }
        float4 oA, oB;
        oA.x = siluf(a0); oA.y = siluf(a1); oA.z = siluf(a2); oA.w = siluf(a3);
        oB.x = siluf(b0); oB.y = siluf(b1); oB.z = siluf(b2); oB.w = siluf(b3);
        *(float4*)(Out + jA*64 + h0) = oA;
        *(float4*)(Out + jB*64 + h0) = oB;
    }
}

// ---------------- kernel 2: phase 1 (128 threads) ----------------
__global__ void __launch_bounds__(128) k_phase1(
    const float* __restrict__ w_embed,
    const float* __restrict__ r1_w0, const float* __restrict__ r1_b0,
    const float* __restrict__ r1_w1, const float* __restrict__ r1_b1,
    const float* __restrict__ r1_w2, const float* __restrict__ r1_b2,
    const float* __restrict__ r1_w3, const float* __restrict__ r1_b3,
    const float* __restrict__ mix_l0, const float* __restrict__ mix_l1,
    const float* __restrict__ mix_l2)
{
    extern __shared__ float sm[];
    float* Xin = sm;            // 512
    float* Ysm = Xin + 512;     // 512 (mask premultiplied)
    float* mk  = Ysm + 512;     // 64
    float* Ha  = mk + 64;       // 4096
    float* Hb  = Ha + 4096;     // 4096 (overlaid by G/S/msg/t2 after L3)
    float* Wb  = Hb + 4096;     // 4096  -> 13376 floats (53.5KB)
    float* G   = Hb;            // 576
    float* S   = Hb + 576;      // 16
    float* msg = Hb + 592;      // 1152
    float* t2  = Hb + 1744;     // 128

    int t = threadIdx.x;
    int node = blockIdx.x;
    int pbase = node * 64;

    for (int idx = t; idx < 512; idx += 128) Xin[idx] = g_rad[(size_t)pbase*8 + idx];
    for (int idx = t; idx < 512; idx += 128)
        Ysm[idx] = g_Y[(size_t)pbase*8 + idx] * g_mask[pbase + (idx >> 3)];
    if (t < 64) mk[t] = g_mask[pbase + t];
    for (int idx = t; idx < 512; idx += 128) Wb[idx] = r1_w0[idx];
    __syncthreads();

    dense_layer<8>(Xin, 8, Wb, r1_b0, Ha, t);
    __syncthreads();
    for (int idx = t; idx < 4096; idx += 128) Wb[idx] = r1_w1[idx];
    __syncthreads();
    dense_layer<64>(Ha, 64, Wb, r1_b1, Hb, t);
    __syncthreads();
    for (int idx = t; idx < 4096; idx += 128) Wb[idx] = r1_w2[idx];
    __syncthreads();
    dense_layer<64>(Hb, 64, Wb, r1_b2, Ha, t);   // final H in Ha; Hb now free
    __syncthreads();

    for (int idx = t; idx < 576; idx += 128) {
        int m = idx >> 6, c = idx & 63;
        float acc = 0.0f;
        #pragma unroll 8
        for (int j = 0; j < 64; ++j) {
            float yv = (m == 0) ? mk[j] : Ysm[j*8 + m - 1];
            acc += yv * Ha[j*64 + c];
        }
        G[idx] = acc;
    }
    if (t < 9) {
        float acc = 0.0f;
        for (int j = 0; j < 64; ++j) acc += (t == 0) ? mk[j] : Ysm[j*8 + t - 1];
        S[t] = acc;
    }
    __syncthreads();

    {
        int k = t;
        float wk = w_embed[k] * 0.0625f;
        float acc[9];
        float b3_0 = r1_b3[k], b3_1 = r1_b3[128 + k], b3_2 = r1_b3[256 + k];
        acc[0] = b3_0 * S[0];
        #pragma unroll
        for (int m = 1; m <= 3; ++m) acc[m] = b3_1 * S[m];
        #pragma unroll
        for (int m = 4; m <= 8; ++m) acc[m] = b3_2 * S[m];
        const float* w3p = r1_w3 + k;
        #pragma unroll 4
        for (int c = 0; c < 64; ++c) {
            float w0 = __ldg(w3p + c*384);
            float w1 = __ldg(w3p + c*384 + 128);
            float w2 = __ldg(w3p + c*384 + 256);
            acc[0] += G[c] * w0;
            acc[1] += G[64 + c]  * w1;
            acc[2] += G[128 + c] * w1;
            acc[3] += G[192 + c] * w1;
            acc[4] += G[256 + c] * w2;
            acc[5] += G[320 + c] * w2;
            acc[6] += G[384 + c] * w2;
            acc[7] += G[448 + c] * w2;
            acc[8] += G[512 + c] * w2;
        }
        #pragma unroll
        for (int m = 0; m < 9; ++m) msg[m*128 + k] = acc[m] * wk;
    }
    __syncthreads();
    {
        float a4 = msg[4*128+t], a5 = msg[5*128+t], a6 = msg[6*128+t],
              a7 = msg[7*128+t], a8 = msg[8*128+t];
        t2[t] = a4*a4 + a5*a5 + a6*a6 + a7*a7 + a8*a8;
    }
    __syncthreads();

    {
        int k = t;
        float s = 0.0f, v0 = 0.0f, v1 = 0.0f, v2 = 0.0f;
        const float* l0p = mix_l0 + k;
        const float* l1p = mix_l1 + k;
        const float* l2p = mix_l2 + k;
        #pragma unroll 4
        for (int c = 0; c < 128; ++c) {
            float w0 = __ldg(l0p + c*128);
            float w1 = __ldg(l1p + c*128);
            float w2 = __ldg(l2p + c*128);
            s  += msg[c]*w0 + t2[c]*w2;
            v0 += msg[128 + c]*w1;
            v1 += msg[256 + c]*w1;
            v2 += msg[384 + c]*w1;
        }
        g_s1[node*128 + k] = s;
        g_h1[node*128 + k] = siluf(s);
        g_v1[(node*3 + 0)*128 + k] = v0;
        g_v1[(node*3 + 1)*128 + k] = v1;
        g_v1[(node*3 + 2)*128 + k] = v2;
    }
}

// ---------------- kernel 3: phase 2 (128 threads) ----------------
__global__ void __launch_bounds__(128) k_phase2(
    const float* __restrict__ r2_w0, const float* __restrict__ r2_b0,
    const float* __restrict__ r2_w1, const float* __restrict__ r2_b1,
    const float* __restrict__ r2_w2, const float* __restrict__ r2_b2,
    const float* __restrict__ r2_w3, const float* __restrict__ r2_b3,
    const float* __restrict__ mix2)
{
    extern __shared__ float sm[];
    float* Xin  = sm;            // 512
    float* mk   = Xin + 512;     // 64
    float* Y1s  = mk + 64;       // 192
    float* Ha   = Y1s + 192;     // 4096
    float* Hb   = Ha + 4096;     // 4096
    float* Wb   = Hb + 4096;     // 4096
    float* msgS = Wb + 4096;     // 128  -> 13184 floats (52.7KB)

    int t = threadIdx.x;
    int node = blockIdx.x;
    int b = node >> 6;
    int pbase = node * 64;

    for (int idx = t; idx < 512; idx += 128) Xin[idx] = g_rad[(size_t)pbase*8 + idx];
    if (t < 64) mk[t] = g_mask[pbase + t];
    for (int idx = t; idx < 192; idx += 128) {
        int j = idx / 3, m = idx - j*3;
        Y1s[idx] = g_Y[(size_t)pbase*8 + j*8 + m] * g_mask[pbase + j];
    }
    for (int idx = t; idx < 512; idx += 128) Wb[idx] = r2_w0[idx];
    __syncthreads();

    dense_layer<8>(Xin, 8, Wb, r2_b0, Ha, t);
    __syncthreads();
    for (int idx = t; idx < 4096; idx += 128) Wb[idx] = r2_w1[idx];
    __syncthreads();
    dense_layer<64>(Ha, 64, Wb, r2_b1, Hb, t);
    __syncthreads();
    for (int idx = t; idx < 4096; idx += 128) Wb[idx] = r2_w2[idx];
    __syncthreads();
    dense_layer<64>(Hb, 64, Wb, r2_b2, Ha, t);   // final H' in Ha
    __syncthreads();

    int k = t;
    float P[64];
    float acc_a, acc_b;
    {
        float sp = 0.0f;
        #pragma unroll
        for (int j = 0; j < 64; ++j) {
            float p = mk[j] * __ldg(g_h1 + (b*64 + j)*128 + k);
            P[j] = p; sp += p;
        }
        float acc = r2_b3[k] * sp;
        #pragma unroll 1
        for (int c = 0; c < 64; c += 4) {
            float w0 = __ldg(r2_w3 + (c+0)*256 + k);
            float w1 = __ldg(r2_w3 + (c+1)*256 + k);
            float w2 = __ldg(r2_w3 + (c+2)*256 + k);
            float w3 = __ldg(r2_w3 + (c+3)*256 + k);
            float s0 = 0.0f, s1 = 0.0f, s2 = 0.0f, s3 = 0.0f;
            #pragma unroll
            for (int j = 0; j < 64; ++j) {
                float4 hv = *(const float4*)(Ha + j*64 + c);
                float pj = P[j];
                s0 += pj*hv.x; s1 += pj*hv.y; s2 += pj*hv.z; s3 += pj*hv.w;
            }
            acc += s0*w0 + s1*w1 + s2*w2 + s3*w3;
        }
        acc_a = acc;
    }
    {
        float sq = 0.0f;
        #pragma unroll
        for (int j = 0; j < 64; ++j) {
            const float* vp = g_v1 + ((size_t)(b*64 + j)*3)*128 + k;
            float q = Y1s[j*3+0]*__ldg(vp) + Y1s[j*3+1]*__ldg(vp+128) + Y1s[j*3+2]*__ldg(vp+256);
            P[j] = q; sq += q;
        }
        float acc = r2_b3[128 + k] * sq;
        #pragma unroll 1
        for (int c = 0; c < 64; c += 4) {
            float w0 = __ldg(r2_w3 + (c+0)*256 + 128 + k);
            float w1 = __ldg(r2_w3 + (c+1)*256 + 128 + k);
            float w2 = __ldg(r2_w3 + (c+2)*256 + 128 + k);
            float w3 = __ldg(r2_w3 + (c+3)*256 + 128 + k);
            float s0 = 0.0f, s1 = 0.0f, s2 = 0.0f, s3 = 0.0f;
            #pragma unroll
            for (int j = 0; j < 64; ++j) {
                float4 hv = *(const float4*)(Ha + j*64 + c);
                float pj = P[j];
                s0 += pj*hv.x; s1 += pj*hv.y; s2 += pj*hv.z; s3 += pj*hv.w;
            }
            acc += s0*w0 + s1*w1 + s2*w2 + s3*w3;
        }
        acc_b = acc;
    }
    msgS[k] = (acc_a + acc_b) * 0.0625f;
    __syncthreads();
    {
        float s2v = 0.0f;
        #pragma unroll 4
        for (int c = 0; c < 128; ++c) s2v += msgS[c] * __ldg(mix2 + c*128 + k);
        g_s2[node*128 + k] = s2v;
    }
}

// ---------------- kernel 4: final MLP (16 nodes/block, stride-18 transposed, FFMA2) ----------------
#define MR 16
#define MST 18
__global__ void __launch_bounds__(512) k_mlp(
    const float* __restrict__ tim,
    const float* __restrict__ w0, const float* __restrict__ b0,
    const float* __restrict__ w1, const float* __restrict__ b1,
    const float* __restrict__ w2, const float* __restrict__ b2,
    float* __restrict__ out)
{
    extern __shared__ float sm[];
    float* xs_t  = sm;                 // [641][18] = 11538
    float* h0s_t = xs_t + 641*MST;     // [512][18] = 9216  -> 20754 floats (83KB)
    float* h1s_t = xs_t;               // overlays xs_t after layer0

    int t = threadIdx.x;
    int rbase = blockIdx.x * MR;

    for (int idx = t; idx < MR*641; idx += 512) {
        int c = idx >> 4, r = idx & (MR-1);
        int node = rbase + r;
        float v;
        if (c < 128)       v = g_s1[node*128 + c];
        else if (c < 512)  v = g_v1[(size_t)node*384 + (c - 128)];
        else if (c < 640)  v = g_s2[node*128 + (c - 512)];
        else               v = tim[node >> 6];
        xs_t[c*MST + r] = v;
    }
    __syncthreads();

    // layer 0: 641 -> 512, relu. thread t = output column; 16 rows as 8 u64.
    {
        u64 acc[8];
        u64 bb = pk2(b0[t], b0[t]);
        #pragma unroll
        for (int i = 0; i < 8; ++i) acc[i] = bb;
        #pragma unroll 4
        for (int c = 0; c < 641; ++c) {
            float w = __ldg(w0 + c*512 + t);
            u64 wp = pk2(w, w);
            const u64* xp = (const u64*)(xs_t + c*MST);
            #pragma unroll
            for (int i = 0; i < 8; ++i) fma2(acc[i], xp[i], wp);
        }
        #pragma unroll
        for (int i = 0; i < 8; ++i) {
            float2 p = upk(acc[i]);
            h0s_t[t*MST + 2*i]     = fmaxf(p.x, 0.0f);
            h0s_t[t*MST + 2*i + 1] = fmaxf(p.y, 0.0f);
        }
    }
    __syncthreads();

    // layer 1: 512 -> 512, relu (writes h1s_t overlaying xs_t)
    {
        u64 acc[8];
        u64 bb = pk2(b1[t], b1[t]);
        #pragma unroll
        for (int i = 0; i < 8; ++i) acc[i] = bb;
        #pragma unroll 4
        for (int c = 0; c < 512; ++c) {
            float w = __ldg(w1 + c*512 + t);
            u64 wp = pk2(w, w);
            const u64* xp = (const u64*)(h0s_t + c*MST);
            #pragma unroll
            for (int i = 0; i < 8; ++i) fma2(acc[i], xp[i], wp);
        }
        #pragma unroll
        for (int i = 0; i < 8; ++i) {
            float2 p = upk(acc[i]);
            h1s_t[t*MST + 2*i]     = fmaxf(p.x, 0.0f);
            h1s_t[t*MST + 2*i + 1] = fmaxf(p.y, 0.0f);
        }
    }
    __syncthreads();

    // layer 2: 512 -> 3 ; warp w (0..15) handles row r = w
    {
        int wid = t >> 5, lane = t & 31;
        int r = wid;
        float p0 = 0.0f, p1 = 0.0f, p2 = 0.0f;
        for (int c = lane; c < 512; c += 32) {
            float hv = h1s_t[c*MST + r];
            p0 += hv * w2[c*3 + 0];
            p1 += hv * w2[c*3 + 1];
            p2 += hv * w2[c*3 + 2];
        }
        #pragma unroll
        for (int off = 16; off > 0; off >>= 1) {
            p0 += __shfl_down_sync(0xffffffffu, p0, off);
            p1 += __shfl_down_sync(0xffffffffu, p1, off);
            p2 += __shfl_down_sync(0xffffffffu, p2, off);
        }
        if (lane == 0) {
            int node = rbase + r;
            out[node*3 + 0] = p0 + b2[0];
            out[node*3 + 1] = p1 + b2[1];
            out[node*3 + 2] = p2 + b2[2];
        }
    }
}

// ---------------- launch ----------------
extern "C" void kernel_launch(void* const* d_in, const int* in_sizes, int n_in,
                              void* d_out, int out_size)
{
    const float* frac    = (const float*)d_in[0];
    const float* tim     = (const float*)d_in[1];
    const float* cell    = (const float*)d_in[2];
    const float* w_embed = (const float*)d_in[3];
    const float* r1_w0 = (const float*)d_in[4];
    const float* r1_b0 = (const float*)d_in[5];
    const float* r1_w1 = (const float*)d_in[6];
    const float* r1_b1 = (const float*)d_in[7];
    const float* r1_w2 = (const float*)d_in[8];
    const float* r1_b2 = (const float*)d_in[9];
    const float* r1_w3 = (const float*)d_in[10];
    const float* r1_b3 = (const float*)d_in[11];
    const float* mix1_l0 = (const float*)d_in[12];
    const float* mix1_l1 = (const float*)d_in[13];
    const float* mix1_l2 = (const float*)d_in[14];
    const float* r2_w0 = (const float*)d_in[15];
    const float* r2_b0 = (const float*)d_in[16];
    const float* r2_w1 = (const float*)d_in[17];
    const float* r2_b1 = (const float*)d_in[18];
    const float* r2_w2 = (const float*)d_in[19];
    const float* r2_b2 = (const float*)d_in[20];
    const float* r2_w3 = (const float*)d_in[21];
    const float* r2_b3 = (const float*)d_in[22];
    const float* mix2  = (const float*)d_in[23];
    const float* mlp_w0 = (const float*)d_in[24];
    const float* mlp_b0 = (const float*)d_in[25];
    const float* mlp_w1 = (const float*)d_in[26];
    const float* mlp_b1 = (const float*)d_in[27];
    const float* mlp_w2 = (const float*)d_in[28];
    const float* mlp_b2 = (const float*)d_in[29];

    const int SM_P1  = 13376 * 4;
    const int SM_P2  = 13184 * 4;
    const int SM_MLP = (641*MST + 512*MST) * 4;

    cudaFuncSetAttribute(k_phase1, cudaFuncAttributeMaxDynamicSharedMemorySize, SM_P1);
    cudaFuncSetAttribute(k_phase2, cudaFuncAttributeMaxDynamicSharedMemorySize, SM_P2);
    cudaFuncSetAttribute(k_mlp,    cudaFuncAttributeMaxDynamicSharedMemorySize, SM_MLP);
    cudaFuncSetAttribute(k_phase1, cudaFuncAttributePreferredSharedMemoryCarveout, 100);
    cudaFuncSetAttribute(k_phase2, cudaFuncAttributePreferredSharedMemoryCarveout, 100);
    cudaFuncSetAttribute(k_mlp,    cudaFuncAttributePreferredSharedMemoryCarveout, 100);

    k_geom<<<NPAIR/256, 256>>>(frac, cell);
    k_phase1<<<NNODE, 128, SM_P1>>>(w_embed,
        r1_w0, r1_b0, r1_w1, r1_b1, r1_w2, r1_b2, r1_w3, r1_b3,
        mix1_l0, mix1_l1, mix1_l2);
    k_phase2<<<NNODE, 128, SM_P2>>>(
        r2_w0, r2_b0, r2_w1, r2_b1, r2_w2, r2_b2, r2_w3, r2_b3, mix2);
    k_mlp<<<NNODE/MR, 512, SM_MLP>>>(tim, mlp_w0, mlp_b0, mlp_w1, mlp_b1,
        mlp_w2, mlp_b2, (float*)d_out);
}

// round 13
// speedup vs baseline: 2.0053x; 1.0150x over previous
#include <cuda_runtime.h>
#include <math.h>

#define BB 32
#define NN 64
#define KK 128
#define NPAIR (BB*NN*NN)
#define NNODE (BB*NN)

__device__ float g_rad[NPAIR*8];
__device__ float g_Y[NPAIR*8];
__device__ float g_mask[NPAIR];
__device__ float g_h1[NNODE*KK];
__device__ float g_s1[NNODE*KK];
__device__ float g_v1[NNODE*3*KK];
__device__ float g_s2[NNODE*KK];

__device__ __forceinline__ float siluf(float x) { return x / (1.0f + __expf(-x)); }

typedef unsigned long long u64;
__device__ __forceinline__ u64 pk2(float lo, float hi) {
    u64 r; asm("mov.b64 %0, {%1,%2};" : "=l"(r) : "f"(lo), "f"(hi)); return r;
}
__device__ __forceinline__ void fma2(u64& a, u64 x, u64 y) {
    asm("fma.rn.f32x2 %0, %1, %2, %3;" : "=l"(a) : "l"(x), "l"(y), "l"(a));
}
__device__ __forceinline__ float2 upk(u64 v) {
    float2 o; asm("mov.b64 {%0,%1}, %2;" : "=f"(o.x), "=f"(o.y) : "l"(v)); return o;
}

// ---------------- kernel 1: pairwise geometry ----------------
__global__ void k_geom(const float* __restrict__ frac, const float* __restrict__ cell)
{
    int idx = blockIdx.x * blockDim.x + threadIdx.x;
    if (idx >= NPAIR) return;
    int b = idx >> 12;
    int i = (idx >> 6) & 63;
    int j = idx & 63;
    const float* fi = frac + (b*NN + i)*3;
    const float* fj = frac + (b*NN + j)*3;
    float d0 = fi[0]-fj[0], d1 = fi[1]-fj[1], d2 = fi[2]-fj[2];
    d0 -= rintf(d0); d1 -= rintf(d1); d2 -= rintf(d2);
    const float* C = cell + b*9;
    float x = d0*C[0] + d1*C[3] + d2*C[6];
    float y = d0*C[1] + d1*C[4] + d2*C[7];
    float z = d0*C[2] + d1*C[5] + d2*C[8];
    float r2 = fmaxf(x*x + y*y + z*z, 1e-12f);
    float r = sqrtf(r2);
    bool m = (r < 5.0f) && (i != j);
    float mf = m ? 1.0f : 0.0f;
    float rs = m ? r : 1.0f;
    float inv = 1.0f / rs;
    float ux = x*inv*mf, uy = y*inv*mf, uz = z*inv*mf;
    float u = rs * 0.2f;
    float u2 = u*u, u4 = u2*u2, u5 = u4*u;
    float fc = 1.0f - 21.0f*u5 + 35.0f*u5*u - 15.0f*u5*u2;
    fc = (u < 1.0f) ? fc : 0.0f;
    float pref = 0.6324555320336759f * inv * fc * mf;
    float w = 0.6283185307179586f * rs;
    float* rp = g_rad + (size_t)idx*8;
    #pragma unroll
    for (int n = 1; n <= 8; ++n) rp[n-1] = pref * sinf((float)n * w);
    const float s3 = 1.7320508075688772f, s5 = 2.23606797749979f, s15 = 3.872983346207417f;
    float* Y = g_Y + (size_t)idx*8;
    Y[0] = s3*ux; Y[1] = s3*uy; Y[2] = s3*uz;
    Y[3] = s15*ux*uy;
    Y[4] = s15*uy*uz;
    Y[5] = 0.5f*s5*(3.0f*uz*uz - 1.0f);
    Y[6] = s15*ux*uz;
    Y[7] = 0.5f*s15*(ux*ux - uy*uy);
    g_mask[idx] = mf;
}

// ---------------- 64-wide dense layer (silu), 2 j-rows per thread ----------------
template<int CDIM>
__device__ __forceinline__ void dense_layer(const float* __restrict__ In, int ldi,
                                            const float* __restrict__ Wsh,
                                            const float* __restrict__ bias,
                                            float* __restrict__ Out, int t)
{
    int jbase = t >> 4;
    int h0 = (t & 15) * 4;
    #pragma unroll 1
    for (int it = 0; it < 4; ++it) {
        int jA = jbase + 8*it;
        int jB = jA + 32;
        float a0 = bias[h0+0], a1 = bias[h0+1], a2 = bias[h0+2], a3 = bias[h0+3];
        float b0 = a0, b1 = a1, b2 = a2, b3 = a3;
        const float* inA = In + jA*ldi;
        const float* inB = In + jB*ldi;
        #pragma unroll 4
        for (int c = 0; c < CDIM; ++c) {
            float av = inA[c];
            float bv = inB[c];
            float4 wv = *(const float4*)(Wsh + c*64 + h0);
            a0 += av*wv.x; a1 += av*wv.y; a2 += av*wv.z; a3 += av*wv.w;
            b0 += bv*wv.x; b1 += bv*wv.y; b2 += bv*wv.z; b3 += bv*wv.w;
        }
        float4 oA, oB;
        oA.x = siluf(a0); oA.y = siluf(a1); oA.z = siluf(a2); oA.w = siluf(a3);
        oB.x = siluf(b0); oB.y = siluf(b1); oB.z = siluf(b2); oB.w = siluf(b3);
        *(float4*)(Out + jA*64 + h0) = oA;
        *(float4*)(Out + jB*64 + h0) = oB;
    }
}

// ---------------- kernel 2: phase 1 (128 threads) ----------------
__global__ void __launch_bounds__(128) k_phase1(
    const float* __restrict__ w_embed,
    const float* __restrict__ r1_w0, const float* __restrict__ r1_b0,
    const float* __restrict__ r1_w1, const float* __restrict__ r1_b1,
    const float* __restrict__ r1_w2, const float* __restrict__ r1_b2,
    const float* __restrict__ r1_w3, const float* __restrict__ r1_b3,
    const float* __restrict__ mix_l0, const float* __restrict__ mix_l1,
    const float* __restrict__ mix_l2)
{
    extern __shared__ float sm[];
    float* Xin = sm;            // 512
    float* Ysm = Xin + 512;     // 512 (mask premultiplied)
    float* mk  = Ysm + 512;     // 64
    float* Ha  = mk + 64;       // 4096
    float* Hb  = Ha + 4096;     // 4096 (overlaid by G/S/msg/t2 after L3)
    float* Wb  = Hb + 4096;     // 4096  -> 13376 floats (53.5KB)
    float* G   = Hb;            // 576
    float* S   = Hb + 576;      // 16
    float* msg = Hb + 592;      // 1152
    float* t2  = Hb + 1744;     // 128

    int t = threadIdx.x;
    int node = blockIdx.x;
    int pbase = node * 64;

    for (int idx = t; idx < 512; idx += 128) Xin[idx] = g_rad[(size_t)pbase*8 + idx];
    for (int idx = t; idx < 512; idx += 128)
        Ysm[idx] = g_Y[(size_t)pbase*8 + idx] * g_mask[pbase + (idx >> 3)];
    if (t < 64) mk[t] = g_mask[pbase + t];
    for (int idx = t; idx < 512; idx += 128) Wb[idx] = r1_w0[idx];
    __syncthreads();

    dense_layer<8>(Xin, 8, Wb, r1_b0, Ha, t);
    __syncthreads();
    for (int idx = t; idx < 4096; idx += 128) Wb[idx] = r1_w1[idx];
    __syncthreads();
    dense_layer<64>(Ha, 64, Wb, r1_b1, Hb, t);
    __syncthreads();
    for (int idx = t; idx < 4096; idx += 128) Wb[idx] = r1_w2[idx];
    __syncthreads();
    dense_layer<64>(Hb, 64, Wb, r1_b2, Ha, t);   // final H in Ha; Hb now free
    __syncthreads();

    for (int idx = t; idx < 576; idx += 128) {
        int m = idx >> 6, c = idx & 63;
        float acc = 0.0f;
        #pragma unroll 8
        for (int j = 0; j < 64; ++j) {
            float yv = (m == 0) ? mk[j] : Ysm[j*8 + m - 1];
            acc += yv * Ha[j*64 + c];
        }
        G[idx] = acc;
    }
    if (t < 9) {
        float acc = 0.0f;
        for (int j = 0; j < 64; ++j) acc += (t == 0) ? mk[j] : Ysm[j*8 + t - 1];
        S[t] = acc;
    }
    __syncthreads();

    {
        int k = t;
        float wk = w_embed[k] * 0.0625f;
        float acc[9];
        float b3_0 = r1_b3[k], b3_1 = r1_b3[128 + k], b3_2 = r1_b3[256 + k];
        acc[0] = b3_0 * S[0];
        #pragma unroll
        for (int m = 1; m <= 3; ++m) acc[m] = b3_1 * S[m];
        #pragma unroll
        for (int m = 4; m <= 8; ++m) acc[m] = b3_2 * S[m];
        const float* w3p = r1_w3 + k;
        #pragma unroll 4
        for (int c = 0; c < 64; ++c) {
            float w0 = __ldg(w3p + c*384);
            float w1 = __ldg(w3p + c*384 + 128);
            float w2 = __ldg(w3p + c*384 + 256);
            acc[0] += G[c] * w0;
            acc[1] += G[64 + c]  * w1;
            acc[2] += G[128 + c] * w1;
            acc[3] += G[192 + c] * w1;
            acc[4] += G[256 + c] * w2;
            acc[5] += G[320 + c] * w2;
            acc[6] += G[384 + c] * w2;
            acc[7] += G[448 + c] * w2;
            acc[8] += G[512 + c] * w2;
        }
        #pragma unroll
        for (int m = 0; m < 9; ++m) msg[m*128 + k] = acc[m] * wk;
    }
    __syncthreads();
    {
        float a4 = msg[4*128+t], a5 = msg[5*128+t], a6 = msg[6*128+t],
              a7 = msg[7*128+t], a8 = msg[8*128+t];
        t2[t] = a4*a4 + a5*a5 + a6*a6 + a7*a7 + a8*a8;
    }
    __syncthreads();

    {
        int k = t;
        float s = 0.0f, v0 = 0.0f, v1 = 0.0f, v2 = 0.0f;
        const float* l0p = mix_l0 + k;
        const float* l1p = mix_l1 + k;
        const float* l2p = mix_l2 + k;
        #pragma unroll 4
        for (int c = 0; c < 128; ++c) {
            float w0 = __ldg(l0p + c*128);
            float w1 = __ldg(l1p + c*128);
            float w2 = __ldg(l2p + c*128);
            s  += msg[c]*w0 + t2[c]*w2;
            v0 += msg[128 + c]*w1;
            v1 += msg[256 + c]*w1;
            v2 += msg[384 + c]*w1;
        }
        g_s1[node*128 + k] = s;
        g_h1[node*128 + k] = siluf(s);
        g_v1[(node*3 + 0)*128 + k] = v0;
        g_v1[(node*3 + 1)*128 + k] = v1;
        g_v1[(node*3 + 2)*128 + k] = v2;
    }
}

// ---------------- kernel 3: phase 2 (128 threads) ----------------
__global__ void __launch_bounds__(128) k_phase2(
    const float* __restrict__ r2_w0, const float* __restrict__ r2_b0,
    const float* __restrict__ r2_w1, const float* __restrict__ r2_b1,
    const float* __restrict__ r2_w2, const float* __restrict__ r2_b2,
    const float* __restrict__ r2_w3, const float* __restrict__ r2_b3,
    const float* __restrict__ mix2)
{
    extern __shared__ float sm[];
    float* Xin  = sm;            // 512
    float* mk   = Xin + 512;     // 64
    float* Y1s  = mk + 64;       // 192
    float* Ha   = Y1s + 192;     // 4096
    float* Hb   = Ha + 4096;     // 4096
    float* Wb   = Hb + 4096;     // 4096
    float* msgS = Wb + 4096;     // 128  -> 13184 floats (52.7KB)

    int t = threadIdx.x;
    int node = blockIdx.x;
    int b = node >> 6;
    int pbase = node * 64;

    for (int idx = t; idx < 512; idx += 128) Xin[idx] = g_rad[(size_t)pbase*8 + idx];
    if (t < 64) mk[t] = g_mask[pbase + t];
    for (int idx = t; idx < 192; idx += 128) {
        int j = idx / 3, m = idx - j*3;
        Y1s[idx] = g_Y[(size_t)pbase*8 + j*8 + m] * g_mask[pbase + j];
    }
    for (int idx = t; idx < 512; idx += 128) Wb[idx] = r2_w0[idx];
    __syncthreads();

    dense_layer<8>(Xin, 8, Wb, r2_b0, Ha, t);
    __syncthreads();
    for (int idx = t; idx < 4096; idx += 128) Wb[idx] = r2_w1[idx];
    __syncthreads();
    dense_layer<64>(Ha, 64, Wb, r2_b1, Hb, t);
    __syncthreads();
    for (int idx = t; idx < 4096; idx += 128) Wb[idx] = r2_w2[idx];
    __syncthreads();
    dense_layer<64>(Hb, 64, Wb, r2_b2, Ha, t);   // final H' in Ha
    __syncthreads();

    int k = t;
    float P[64];
    float acc_a, acc_b;
    {
        float sp = 0.0f;
        #pragma unroll
        for (int j = 0; j < 64; ++j) {
            float p = mk[j] * __ldg(g_h1 + (b*64 + j)*128 + k);
            P[j] = p; sp += p;
        }
        float acc = r2_b3[k] * sp;
        #pragma unroll 1
        for (int c = 0; c < 64; c += 4) {
            float w0 = __ldg(r2_w3 + (c+0)*256 + k);
            float w1 = __ldg(r2_w3 + (c+1)*256 + k);
            float w2 = __ldg(r2_w3 + (c+2)*256 + k);
            float w3 = __ldg(r2_w3 + (c+3)*256 + k);
            float s0 = 0.0f, s1 = 0.0f, s2 = 0.0f, s3 = 0.0f;
            #pragma unroll
            for (int j = 0; j < 64; ++j) {
                float4 hv = *(const float4*)(Ha + j*64 + c);
                float pj = P[j];
                s0 += pj*hv.x; s1 += pj*hv.y; s2 += pj*hv.z; s3 += pj*hv.w;
            }
            acc += s0*w0 + s1*w1 + s2*w2 + s3*w3;
        }
        acc_a = acc;
    }
    {
        float sq = 0.0f;
        #pragma unroll
        for (int j = 0; j < 64; ++j) {
            const float* vp = g_v1 + ((size_t)(b*64 + j)*3)*128 + k;
            float q = Y1s[j*3+0]*__ldg(vp) + Y1s[j*3+1]*__ldg(vp+128) + Y1s[j*3+2]*__ldg(vp+256);
            P[j] = q; sq += q;
        }
        float acc = r2_b3[128 + k] * sq;
        #pragma unroll 1
        for (int c = 0; c < 64; c += 4) {
            float w0 = __ldg(r2_w3 + (c+0)*256 + 128 + k);
            float w1 = __ldg(r2_w3 + (c+1)*256 + 128 + k);
            float w2 = __ldg(r2_w3 + (c+2)*256 + 128 + k);
            float w3 = __ldg(r2_w3 + (c+3)*256 + 128 + k);
            float s0 = 0.0f, s1 = 0.0f, s2 = 0.0f, s3 = 0.0f;
            #pragma unroll
            for (int j = 0; j < 64; ++j) {
                float4 hv = *(const float4*)(Ha + j*64 + c);
                float pj = P[j];
                s0 += pj*hv.x; s1 += pj*hv.y; s2 += pj*hv.z; s3 += pj*hv.w;
            }
            acc += s0*w0 + s1*w1 + s2*w2 + s3*w3;
        }
        acc_b = acc;
    }
    msgS[k] = (acc_a + acc_b) * 0.0625f;
    __syncthreads();
    {
        float s2v = 0.0f;
        #pragma unroll 4
        for (int c = 0; c < 128; ++c) s2v += msgS[c] * __ldg(mix2 + c*128 + k);
        g_s2[node*128 + k] = s2v;
    }
}

// ---------------- kernel 4: final MLP (8 nodes/block, 256 thr, 2 cols/thread, FFMA2) ----------------
__global__ void __launch_bounds__(256) k_mlp(
    const float* __restrict__ tim,
    const float* __restrict__ w0, const float* __restrict__ b0,
    const float* __restrict__ w1, const float* __restrict__ b1,
    const float* __restrict__ w2, const float* __restrict__ b2,
    float* __restrict__ out)
{
    extern __shared__ float sm[];
    float* xs_t  = sm;              // [641][8] = 5128
    float* h0s_t = xs_t + 5128;     // [512][8] = 4096  -> 9224 floats (36.9KB)
    float* h1s_t = xs_t;            // overlays xs_t after layer0

    int t = threadIdx.x;
    int rbase = blockIdx.x * 8;

    for (int idx = t; idx < 8*641; idx += 256) {
        int c = idx >> 3, r = idx & 7;
        int node = rbase + r;
        float v;
        if (c < 128)       v = g_s1[node*128 + c];
        else if (c < 512)  v = g_v1[(size_t)node*384 + (c - 128)];
        else if (c < 640)  v = g_s2[node*128 + (c - 512)];
        else               v = tim[node >> 6];
        xs_t[c*8 + r] = v;
    }
    __syncthreads();

    // layer 0: 641 -> 512, relu. thread t handles output cols t and t+256.
    {
        u64 accA[4], accB[4];
        u64 bbA = pk2(b0[t], b0[t]);
        u64 bbB = pk2(b0[t+256], b0[t+256]);
        #pragma unroll
        for (int i = 0; i < 4; ++i) { accA[i] = bbA; accB[i] = bbB; }
        #pragma unroll 4
        for (int c = 0; c < 641; ++c) {
            float wa = __ldg(w0 + c*512 + t);
            float wb = __ldg(w0 + c*512 + t + 256);
            u64 wpA = pk2(wa, wa);
            u64 wpB = pk2(wb, wb);
            const longlong2* xp = (const longlong2*)(xs_t + c*8);
            longlong2 qa = xp[0], qb = xp[1];
            fma2(accA[0], (u64)qa.x, wpA); fma2(accA[1], (u64)qa.y, wpA);
            fma2(accA[2], (u64)qb.x, wpA); fma2(accA[3], (u64)qb.y, wpA);
            fma2(accB[0], (u64)qa.x, wpB); fma2(accB[1], (u64)qa.y, wpB);
            fma2(accB[2], (u64)qb.x, wpB); fma2(accB[3], (u64)qb.y, wpB);
        }
        #pragma unroll
        for (int i = 0; i < 4; ++i) {
            float2 pA = upk(accA[i]);
            float2 pB = upk(accB[i]);
            h0s_t[t*8 + 2*i]           = fmaxf(pA.x, 0.0f);
            h0s_t[t*8 + 2*i + 1]       = fmaxf(pA.y, 0.0f);
            h0s_t[(t+256)*8 + 2*i]     = fmaxf(pB.x, 0.0f);
            h0s_t[(t+256)*8 + 2*i + 1] = fmaxf(pB.y, 0.0f);
        }
    }
    __syncthreads();

    // layer 1: 512 -> 512, relu (writes h1s_t overlaying xs_t)
    {
        u64 accA[4], accB[4];
        u64 bbA = pk2(b1[t], b1[t]);
        u64 bbB = pk2(b1[t+256], b1[t+256]);
        #pragma unroll
        for (int i = 0; i < 4; ++i) { accA[i] = bbA; accB[i] = bbB; }
        #pragma unroll 4
        for (int c = 0; c < 512; ++c) {
            float wa = __ldg(w1 + c*512 + t);
            float wb = __ldg(w1 + c*512 + t + 256);
            u64 wpA = pk2(wa, wa);
            u64 wpB = pk2(wb, wb);
            const longlong2* xp = (const longlong2*)(h0s_t + c*8);
            longlong2 qa = xp[0], qb = xp[1];
            fma2(accA[0], (u64)qa.x, wpA); fma2(accA[1], (u64)qa.y, wpA);
            fma2(accA[2], (u64)qb.x, wpA); fma2(accA[3], (u64)qb.y, wpA);
            fma2(accB[0], (u64)qa.x, wpB); fma2(accB[1], (u64)qa.y, wpB);
            fma2(accB[2], (u64)qb.x, wpB); fma2(accB[3], (u64)qb.y, wpB);
        }
        #pragma unroll
        for (int i = 0; i < 4; ++i) {
            float2 pA = upk(accA[i]);
            float2 pB = upk(accB[i]);
            h1s_t[t*8 + 2*i]           = fmaxf(pA.x, 0.0f);
            h1s_t[t*8 + 2*i + 1]       = fmaxf(pA.y, 0.0f);
            h1s_t[(t+256)*8 + 2*i]     = fmaxf(pB.x, 0.0f);
            h1s_t[(t+256)*8 + 2*i + 1] = fmaxf(pB.y, 0.0f);
        }
    }
    __syncthreads();

    // layer 2: 512 -> 3 ; warp w (0..7) handles row r = w
    {
        int wid = t >> 5, lane = t & 31;
        int r = wid;
        float p0 = 0.0f, p1 = 0.0f, p2 = 0.0f;
        for (int c = lane; c < 512; c += 32) {
            float hv = h1s_t[c*8 + r];
            p0 += hv * w2[c*3 + 0];
            p1 += hv * w2[c*3 + 1];
            p2 += hv * w2[c*3 + 2];
        }
        #pragma unroll
        for (int off = 16; off > 0; off >>= 1) {
            p0 += __shfl_down_sync(0xffffffffu, p0, off);
            p1 += __shfl_down_sync(0xffffffffu, p1, off);
            p2 += __shfl_down_sync(0xffffffffu, p2, off);
        }
        if (lane == 0) {
            int node = rbase + r;
            out[node*3 + 0] = p0 + b2[0];
            out[node*3 + 1] = p1 + b2[1];
            out[node*3 + 2] = p2 + b2[2];
        }
    }
}

// ---------------- launch ----------------
extern "C" void kernel_launch(void* const* d_in, const int* in_sizes, int n_in,
                              void* d_out, int out_size)
{
    const float* frac    = (const float*)d_in[0];
    const float* tim     = (const float*)d_in[1];
    const float* cell    = (const float*)d_in[2];
    const float* w_embed = (const float*)d_in[3];
    const float* r1_w0 = (const float*)d_in[4];
    const float* r1_b0 = (const float*)d_in[5];
    const float* r1_w1 = (const float*)d_in[6];
    const float* r1_b1 = (const float*)d_in[7];
    const float* r1_w2 = (const float*)d_in[8];
    const float* r1_b2 = (const float*)d_in[9];
    const float* r1_w3 = (const float*)d_in[10];
    const float* r1_b3 = (const float*)d_in[11];
    const float* mix1_l0 = (const float*)d_in[12];
    const float* mix1_l1 = (const float*)d_in[13];
    const float* mix1_l2 = (const float*)d_in[14];
    const float* r2_w0 = (const float*)d_in[15];
    const float* r2_b0 = (const float*)d_in[16];
    const float* r2_w1 = (const float*)d_in[17];
    const float* r2_b1 = (const float*)d_in[18];
    const float* r2_w2 = (const float*)d_in[19];
    const float* r2_b2 = (const float*)d_in[20];
    const float* r2_w3 = (const float*)d_in[21];
    const float* r2_b3 = (const float*)d_in[22];
    const float* mix2  = (const float*)d_in[23];
    const float* mlp_w0 = (const float*)d_in[24];
    const float* mlp_b0 = (const float*)d_in[25];
    const float* mlp_w1 = (const float*)d_in[26];
    const float* mlp_b1 = (const float*)d_in[27];
    const float* mlp_w2 = (const float*)d_in[28];
    const float* mlp_b2 = (const float*)d_in[29];

    const int SM_P1  = 13376 * 4;
    const int SM_P2  = 13184 * 4;
    const int SM_MLP = (5128 + 4096) * 4;

    cudaFuncSetAttribute(k_phase1, cudaFuncAttributeMaxDynamicSharedMemorySize, SM_P1);
    cudaFuncSetAttribute(k_phase2, cudaFuncAttributeMaxDynamicSharedMemorySize, SM_P2);
    cudaFuncSetAttribute(k_mlp,    cudaFuncAttributeMaxDynamicSharedMemorySize, SM_MLP);
    cudaFuncSetAttribute(k_phase1, cudaFuncAttributePreferredSharedMemoryCarveout, 100);
    cudaFuncSetAttribute(k_phase2, cudaFuncAttributePreferredSharedMemoryCarveout, 100);
    cudaFuncSetAttribute(k_mlp,    cudaFuncAttributePreferredSharedMemoryCarveout, 100);

    k_geom<<<NPAIR/256, 256>>>(frac, cell);
    k_phase1<<<NNODE, 128, SM_P1>>>(w_embed,
        r1_w0, r1_b0, r1_w1, r1_b1, r1_w2, r1_b2, r1_w3, r1_b3,
        mix1_l0, mix1_l1, mix1_l2);
    k_phase2<<<NNODE, 128, SM_P2>>>(
        r2_w0, r2_b0, r2_w1, r2_b1, r2_w2, r2_b2, r2_w3, r2_b3, mix2);
    k_mlp<<<NNODE/8, 256, SM_MLP>>>(tim, mlp_w0, mlp_b0, mlp_w1, mlp_b1,
        mlp_w2, mlp_b2, (float*)d_out);
}

// round 14
// speedup vs baseline: 2.0777x; 1.0361x over previous
#include <cuda_runtime.h>
#include <math.h>

#define BB 32
#define NN 64
#define KK 128
#define NPAIR (BB*NN*NN)
#define NNODE (BB*NN)

__device__ float g_rad[NPAIR*8];
__device__ float g_Y[NPAIR*8];
__device__ float g_mask[NPAIR];
__device__ float g_h1[NNODE*KK];
__device__ float g_s1[NNODE*KK];
__device__ float g_v1[NNODE*3*KK];
__device__ float g_s2[NNODE*KK];

__device__ __forceinline__ float siluf(float x) { return x / (1.0f + __expf(-x)); }

typedef unsigned long long u64;
__device__ __forceinline__ u64 pk2(float lo, float hi) {
    u64 r; asm("mov.b64 %0, {%1,%2};" : "=l"(r) : "f"(lo), "f"(hi)); return r;
}
__device__ __forceinline__ void fma2(u64& a, u64 x, u64 y) {
    asm("fma.rn.f32x2 %0, %1, %2, %3;" : "=l"(a) : "l"(x), "l"(y), "l"(a));
}
__device__ __forceinline__ float2 upk(u64 v) {
    float2 o; asm("mov.b64 {%0,%1}, %2;" : "=f"(o.x), "=f"(o.y) : "l"(v)); return o;
}

// ---------------- kernel 1: pairwise geometry ----------------
__global__ void k_geom(const float* __restrict__ frac, const float* __restrict__ cell)
{
    int idx = blockIdx.x * blockDim.x + threadIdx.x;
    if (idx >= NPAIR) return;
    int b = idx >> 12;
    int i = (idx >> 6) & 63;
    int j = idx & 63;
    const float* fi = frac + (b*NN + i)*3;
    const float* fj = frac + (b*NN + j)*3;
    float d0 = fi[0]-fj[0], d1 = fi[1]-fj[1], d2 = fi[2]-fj[2];
    d0 -= rintf(d0); d1 -= rintf(d1); d2 -= rintf(d2);
    const float* C = cell + b*9;
    float x = d0*C[0] + d1*C[3] + d2*C[6];
    float y = d0*C[1] + d1*C[4] + d2*C[7];
    float z = d0*C[2] + d1*C[5] + d2*C[8];
    float r2 = fmaxf(x*x + y*y + z*z, 1e-12f);
    float r = sqrtf(r2);
    bool m = (r < 5.0f) && (i != j);
    float mf = m ? 1.0f : 0.0f;
    float rs = m ? r : 1.0f;
    float inv = 1.0f / rs;
    float ux = x*inv*mf, uy = y*inv*mf, uz = z*inv*mf;
    float u = rs * 0.2f;
    float u2 = u*u, u4 = u2*u2, u5 = u4*u;
    float fc = 1.0f - 21.0f*u5 + 35.0f*u5*u - 15.0f*u5*u2;
    fc = (u < 1.0f) ? fc : 0.0f;
    float pref = 0.6324555320336759f * inv * fc * mf;
    float w = 0.6283185307179586f * rs;
    float* rp = g_rad + (size_t)idx*8;
    #pragma unroll
    for (int n = 1; n <= 8; ++n) rp[n-1] = pref * sinf((float)n * w);
    const float s3 = 1.7320508075688772f, s5 = 2.23606797749979f, s15 = 3.872983346207417f;
    float* Y = g_Y + (size_t)idx*8;
    Y[0] = s3*ux; Y[1] = s3*uy; Y[2] = s3*uz;
    Y[3] = s15*ux*uy;
    Y[4] = s15*uy*uz;
    Y[5] = 0.5f*s5*(3.0f*uz*uz - 1.0f);
    Y[6] = s15*ux*uz;
    Y[7] = 0.5f*s15*(ux*ux - uy*uy);
    g_mask[idx] = mf;
}

// ---------------- 64-wide dense layer (silu), 2j x 4c blocking ----------------
// In: [64][ldi] smem (ldi multiple of 4), Wsh: [CDIM][64] smem, Out: [64][64].
// Per 4c: 2 LDS128 (inputs) + 4 LDS128 (weights) for 32 FMA.
template<int CDIM>
__device__ __forceinline__ void dense_layer(const float* __restrict__ In, int ldi,
                                            const float* __restrict__ Wsh,
                                            const float* __restrict__ bias,
                                            float* __restrict__ Out, int t)
{
    int jbase = t >> 4;
    int h0 = (t & 15) * 4;
    #pragma unroll 1
    for (int it = 0; it < 4; ++it) {
        int jA = jbase + 8*it;
        int jB = jA + 32;
        float a0 = bias[h0+0], a1 = bias[h0+1], a2 = bias[h0+2], a3 = bias[h0+3];
        float b0 = a0, b1 = a1, b2 = a2, b3 = a3;
        const float* inA = In + jA*ldi;
        const float* inB = In + jB*ldi;
        #pragma unroll 2
        for (int c = 0; c < CDIM; c += 4) {
            float4 av4 = *(const float4*)(inA + c);
            float4 bv4 = *(const float4*)(inB + c);
            float aarr[4] = {av4.x, av4.y, av4.z, av4.w};
            float barr[4] = {bv4.x, bv4.y, bv4.z, bv4.w};
            #pragma unroll
            for (int d = 0; d < 4; ++d) {
                float4 wv = *(const float4*)(Wsh + (c+d)*64 + h0);
                float av = aarr[d], bv = barr[d];
                a0 += av*wv.x; a1 += av*wv.y; a2 += av*wv.z; a3 += av*wv.w;
                b0 += bv*wv.x; b1 += bv*wv.y; b2 += bv*wv.z; b3 += bv*wv.w;
            }
        }
        float4 oA, oB;
        oA.x = siluf(a0); oA.y = siluf(a1); oA.z = siluf(a2); oA.w = siluf(a3);
        oB.x = siluf(b0); oB.y = siluf(b1); oB.z = siluf(b2); oB.w = siluf(b3);
        *(float4*)(Out + jA*64 + h0) = oA;
        *(float4*)(Out + jB*64 + h0) = oB;
    }
}

// ---------------- kernel 2: phase 1 (128 threads) ----------------
__global__ void __launch_bounds__(128) k_phase1(
    const float* __restrict__ w_embed,
    const float* __restrict__ r1_w0, const float* __restrict__ r1_b0,
    const float* __restrict__ r1_w1, const float* __restrict__ r1_b1,
    const float* __restrict__ r1_w2, const float* __restrict__ r1_b2,
    const float* __restrict__ r1_w3, const float* __restrict__ r1_b3,
    const float* __restrict__ mix_l0, const float* __restrict__ mix_l1,
    const float* __restrict__ mix_l2)
{
    extern __shared__ float sm[];
    float* Xin = sm;            // 512
    float* Ysm = Xin + 512;     // 512 (mask premultiplied)
    float* mk  = Ysm + 512;     // 64
    float* Ha  = mk + 64;       // 4096
    float* Hb  = Ha + 4096;     // 4096 (overlaid by G/S/msg/t2 after L3)
    float* Wb  = Hb + 4096;     // 4096  -> 13376 floats (53.5KB)
    float* G   = Hb;            // 576
    float* S   = Hb + 576;      // 16
    float* msg = Hb + 592;      // 1152
    float* t2  = Hb + 1744;     // 128

    int t = threadIdx.x;
    int node = blockIdx.x;
    int pbase = node * 64;

    for (int idx = t; idx < 512; idx += 128) Xin[idx] = g_rad[(size_t)pbase*8 + idx];
    for (int idx = t; idx < 512; idx += 128)
        Ysm[idx] = g_Y[(size_t)pbase*8 + idx] * g_mask[pbase + (idx >> 3)];
    if (t < 64) mk[t] = g_mask[pbase + t];
    for (int idx = t; idx < 512; idx += 128) Wb[idx] = r1_w0[idx];
    __syncthreads();

    dense_layer<8>(Xin, 8, Wb, r1_b0, Ha, t);
    __syncthreads();
    for (int idx = t; idx < 4096; idx += 128) Wb[idx] = r1_w1[idx];
    __syncthreads();
    dense_layer<64>(Ha, 64, Wb, r1_b1, Hb, t);
    __syncthreads();
    for (int idx = t; idx < 4096; idx += 128) Wb[idx] = r1_w2[idx];
    __syncthreads();
    dense_layer<64>(Hb, 64, Wb, r1_b2, Ha, t);   // final H in Ha; Hb now free
    __syncthreads();

    for (int idx = t; idx < 576; idx += 128) {
        int m = idx >> 6, c = idx & 63;
        float acc = 0.0f;
        #pragma unroll 8
        for (int j = 0; j < 64; ++j) {
            float yv = (m == 0) ? mk[j] : Ysm[j*8 + m - 1];
            acc += yv * Ha[j*64 + c];
        }
        G[idx] = acc;
    }
    if (t < 9) {
        float acc = 0.0f;
        for (int j = 0; j < 64; ++j) acc += (t == 0) ? mk[j] : Ysm[j*8 + t - 1];
        S[t] = acc;
    }
    __syncthreads();

    {
        int k = t;
        float wk = w_embed[k] * 0.0625f;
        float acc[9];
        float b3_0 = r1_b3[k], b3_1 = r1_b3[128 + k], b3_2 = r1_b3[256 + k];
        acc[0] = b3_0 * S[0];
        #pragma unroll
        for (int m = 1; m <= 3; ++m) acc[m] = b3_1 * S[m];
        #pragma unroll
        for (int m = 4; m <= 8; ++m) acc[m] = b3_2 * S[m];
        const float* w3p = r1_w3 + k;
        #pragma unroll 4
        for (int c = 0; c < 64; ++c) {
            float w0 = __ldg(w3p + c*384);
            float w1 = __ldg(w3p + c*384 + 128);
            float w2 = __ldg(w3p + c*384 + 256);
            acc[0] += G[c] * w0;
            acc[1] += G[64 + c]  * w1;
            acc[2] += G[128 + c] * w1;
            acc[3] += G[192 + c] * w1;
            acc[4] += G[256 + c] * w2;
            acc[5] += G[320 + c] * w2;
            acc[6] += G[384 + c] * w2;
            acc[7] += G[448 + c] * w2;
            acc[8] += G[512 + c] * w2;
        }
        #pragma unroll
        for (int m = 0; m < 9; ++m) msg[m*128 + k] = acc[m] * wk;
    }
    __syncthreads();
    {
        float a4 = msg[4*128+t], a5 = msg[5*128+t], a6 = msg[6*128+t],
              a7 = msg[7*128+t], a8 = msg[8*128+t];
        t2[t] = a4*a4 + a5*a5 + a6*a6 + a7*a7 + a8*a8;
    }
    __syncthreads();

    {
        int k = t;
        float s = 0.0f, v0 = 0.0f, v1 = 0.0f, v2 = 0.0f;
        const float* l0p = mix_l0 + k;
        const float* l1p = mix_l1 + k;
        const float* l2p = mix_l2 + k;
        #pragma unroll 4
        for (int c = 0; c < 128; ++c) {
            float w0 = __ldg(l0p + c*128);
            float w1 = __ldg(l1p + c*128);
            float w2 = __ldg(l2p + c*128);
            s  += msg[c]*w0 + t2[c]*w2;
            v0 += msg[128 + c]*w1;
            v1 += msg[256 + c]*w1;
            v2 += msg[384 + c]*w1;
        }
        g_s1[node*128 + k] = s;
        g_h1[node*128 + k] = siluf(s);
        g_v1[(node*3 + 0)*128 + k] = v0;
        g_v1[(node*3 + 1)*128 + k] = v1;
        g_v1[(node*3 + 2)*128 + k] = v2;
    }
}

// ---------------- kernel 3: phase 2 (128 threads) ----------------
__global__ void __launch_bounds__(128) k_phase2(
    const float* __restrict__ r2_w0, const float* __restrict__ r2_b0,
    const float* __restrict__ r2_w1, const float* __restrict__ r2_b1,
    const float* __restrict__ r2_w2, const float* __restrict__ r2_b2,
    const float* __restrict__ r2_w3, const float* __restrict__ r2_b3,
    const float* __restrict__ mix2)
{
    extern __shared__ float sm[];
    float* Xin  = sm;            // 512
    float* mk   = Xin + 512;     // 64
    float* Y1s  = mk + 64;       // 192
    float* Ha   = Y1s + 192;     // 4096
    float* Hb   = Ha + 4096;     // 4096
    float* Wb   = Hb + 4096;     // 4096
    float* msgS = Wb + 4096;     // 128  -> 13184 floats (52.7KB)

    int t = threadIdx.x;
    int node = blockIdx.x;
    int b = node >> 6;
    int pbase = node * 64;

    for (int idx = t; idx < 512; idx += 128) Xin[idx] = g_rad[(size_t)pbase*8 + idx];
    if (t < 64) mk[t] = g_mask[pbase + t];
    for (int idx = t; idx < 192; idx += 128) {
        int j = idx / 3, m = idx - j*3;
        Y1s[idx] = g_Y[(size_t)pbase*8 + j*8 + m] * g_mask[pbase + j];
    }
    for (int idx = t; idx < 512; idx += 128) Wb[idx] = r2_w0[idx];
    __syncthreads();

    dense_layer<8>(Xin, 8, Wb, r2_b0, Ha, t);
    __syncthreads();
    for (int idx = t; idx < 4096; idx += 128) Wb[idx] = r2_w1[idx];
    __syncthreads();
    dense_layer<64>(Ha, 64, Wb, r2_b1, Hb, t);
    __syncthreads();
    for (int idx = t; idx < 4096; idx += 128) Wb[idx] = r2_w2[idx];
    __syncthreads();
    dense_layer<64>(Hb, 64, Wb, r2_b2, Ha, t);   // final H' in Ha
    __syncthreads();

    int k = t;
    float P[64];
    float acc_a, acc_b;
    {
        float sp = 0.0f;
        #pragma unroll
        for (int j = 0; j < 64; ++j) {
            float p = mk[j] * __ldg(g_h1 + (b*64 + j)*128 + k);
            P[j] = p; sp += p;
        }
        float acc = r2_b3[k] * sp;
        #pragma unroll 1
        for (int c = 0; c < 64; c += 4) {
            float w0 = __ldg(r2_w3 + (c+0)*256 + k);
            float w1 = __ldg(r2_w3 + (c+1)*256 + k);
            float w2 = __ldg(r2_w3 + (c+2)*256 + k);
            float w3 = __ldg(r2_w3 + (c+3)*256 + k);
            float s0 = 0.0f, s1 = 0.0f, s2 = 0.0f, s3 = 0.0f;
            #pragma unroll
            for (int j = 0; j < 64; ++j) {
                float4 hv = *(const float4*)(Ha + j*64 + c);
                float pj = P[j];
                s0 += pj*hv.x; s1 += pj*hv.y; s2 += pj*hv.z; s3 += pj*hv.w;
            }
            acc += s0*w0 + s1*w1 + s2*w2 + s3*w3;
        }
        acc_a = acc;
    }
    {
        float sq = 0.0f;
        #pragma unroll
        for (int j = 0; j < 64; ++j) {
            const float* vp = g_v1 + ((size_t)(b*64 + j)*3)*128 + k;
            float q = Y1s[j*3+0]*__ldg(vp) + Y1s[j*3+1]*__ldg(vp+128) + Y1s[j*3+2]*__ldg(vp+256);
            P[j] = q; sq += q;
        }
        float acc = r2_b3[128 + k] * sq;
        #pragma unroll 1
        for (int c = 0; c < 64; c += 4) {
            float w0 = __ldg(r2_w3 + (c+0)*256 + 128 + k);
            float w1 = __ldg(r2_w3 + (c+1)*256 + 128 + k);
            float w2 = __ldg(r2_w3 + (c+2)*256 + 128 + k);
            float w3 = __ldg(r2_w3 + (c+3)*256 + 128 + k);
            float s0 = 0.0f, s1 = 0.0f, s2 = 0.0f, s3 = 0.0f;
            #pragma unroll
            for (int j = 0; j < 64; ++j) {
                float4 hv = *(const float4*)(Ha + j*64 + c);
                float pj = P[j];
                s0 += pj*hv.x; s1 += pj*hv.y; s2 += pj*hv.z; s3 += pj*hv.w;
            }
            acc += s0*w0 + s1*w1 + s2*w2 + s3*w3;
        }
        acc_b = acc;
    }
    msgS[k] = (acc_a + acc_b) * 0.0625f;
    __syncthreads();
    {
        float s2v = 0.0f;
        #pragma unroll 4
        for (int c = 0; c < 128; ++c) s2v += msgS[c] * __ldg(mix2 + c*128 + k);
        g_s2[node*128 + k] = s2v;
    }
}

// ---------------- kernel 4: final MLP (R10-exact: 8 nodes/block, 512 thr, FFMA2, unroll 8) ----------------
__global__ void __launch_bounds__(512) k_mlp(
    const float* __restrict__ tim,
    const float* __restrict__ w0, const float* __restrict__ b0,
    const float* __restrict__ w1, const float* __restrict__ b1,
    const float* __restrict__ w2, const float* __restrict__ b2,
    float* __restrict__ out)
{
    extern __shared__ float sm[];
    float* xs_t  = sm;              // [641][8] = 5128
    float* h0s_t = xs_t + 5128;     // [512][8] = 4096  -> 9224 floats (36.9KB)
    float* h1s_t = xs_t;            // overlays xs_t after layer0

    int t = threadIdx.x;
    int rbase = blockIdx.x * 8;

    for (int idx = t; idx < 8*641; idx += 512) {
        int c = idx >> 3, r = idx & 7;
        int node = rbase + r;
        float v;
        if (c < 128)       v = g_s1[node*128 + c];
        else if (c < 512)  v = g_v1[(size_t)node*384 + (c - 128)];
        else if (c < 640)  v = g_s2[node*128 + (c - 512)];
        else               v = tim[node >> 6];
        xs_t[c*8 + r] = v;
    }
    __syncthreads();

    {
        u64 acc[4];
        u64 bb = pk2(b0[t], b0[t]);
        #pragma unroll
        for (int i = 0; i < 4; ++i) acc[i] = bb;
        #pragma unroll 8
        for (int c = 0; c < 641; ++c) {
            float w = __ldg(w0 + c*512 + t);
            u64 wp = pk2(w, w);
            const longlong2* xp = (const longlong2*)(xs_t + c*8);
            longlong2 qa = xp[0], qb = xp[1];
            fma2(acc[0], (u64)qa.x, wp); fma2(acc[1], (u64)qa.y, wp);
            fma2(acc[2], (u64)qb.x, wp); fma2(acc[3], (u64)qb.y, wp);
        }
        #pragma unroll
        for (int i = 0; i < 4; ++i) {
            float2 p = upk(acc[i]);
            h0s_t[t*8 + 2*i]     = fmaxf(p.x, 0.0f);
            h0s_t[t*8 + 2*i + 1] = fmaxf(p.y, 0.0f);
        }
    }
    __syncthreads();

    {
        u64 acc[4];
        u64 bb = pk2(b1[t], b1[t]);
        #pragma unroll
        for (int i = 0; i < 4; ++i) acc[i] = bb;
        #pragma unroll 8
        for (int c = 0; c < 512; ++c) {
            float w = __ldg(w1 + c*512 + t);
            u64 wp = pk2(w, w);
            const longlong2* xp = (const longlong2*)(h0s_t + c*8);
            longlong2 qa = xp[0], qb = xp[1];
            fma2(acc[0], (u64)qa.x, wp); fma2(acc[1], (u64)qa.y, wp);
            fma2(acc[2], (u64)qb.x, wp); fma2(acc[3], (u64)qb.y, wp);
        }
        #pragma unroll
        for (int i = 0; i < 4; ++i) {
            float2 p = upk(acc[i]);
            h1s_t[t*8 + 2*i]     = fmaxf(p.x, 0.0f);
            h1s_t[t*8 + 2*i + 1] = fmaxf(p.y, 0.0f);
        }
    }
    __syncthreads();

    {
        int wid = t >> 5, lane = t & 31;
        if (wid < 8) {
            int r = wid;
            float p0 = 0.0f, p1 = 0.0f, p2 = 0.0f;
            for (int c = lane; c < 512; c += 32) {
                float hv = h1s_t[c*8 + r];
                p0 += hv * w2[c*3 + 0];
                p1 += hv * w2[c*3 + 1];
                p2 += hv * w2[c*3 + 2];
            }
            #pragma unroll
            for (int off = 16; off > 0; off >>= 1) {
                p0 += __shfl_down_sync(0xffffffffu, p0, off);
                p1 += __shfl_down_sync(0xffffffffu, p1, off);
                p2 += __shfl_down_sync(0xffffffffu, p2, off);
            }
            if (lane == 0) {
                int node = rbase + r;
                out[node*3 + 0] = p0 + b2[0];
                out[node*3 + 1] = p1 + b2[1];
                out[node*3 + 2] = p2 + b2[2];
            }
        }
    }
}

// ---------------- launch ----------------
extern "C" void kernel_launch(void* const* d_in, const int* in_sizes, int n_in,
                              void* d_out, int out_size)
{
    const float* frac    = (const float*)d_in[0];
    const float* tim     = (const float*)d_in[1];
    const float* cell    = (const float*)d_in[2];
    const float* w_embed = (const float*)d_in[3];
    const float* r1_w0 = (const float*)d_in[4];
    const float* r1_b0 = (const float*)d_in[5];
    const float* r1_w1 = (const float*)d_in[6];
    const float* r1_b1 = (const float*)d_in[7];
    const float* r1_w2 = (const float*)d_in[8];
    const float* r1_b2 = (const float*)d_in[9];
    const float* r1_w3 = (const float*)d_in[10];
    const float* r1_b3 = (const float*)d_in[11];
    const float* mix1_l0 = (const float*)d_in[12];
    const float* mix1_l1 = (const float*)d_in[13];
    const float* mix1_l2 = (const float*)d_in[14];
    const float* r2_w0 = (const float*)d_in[15];
    const float* r2_b0 = (const float*)d_in[16];
    const float* r2_w1 = (const float*)d_in[17];
    const float* r2_b1 = (const float*)d_in[18];
    const float* r2_w2 = (const float*)d_in[19];
    const float* r2_b2 = (const float*)d_in[20];
    const float* r2_w3 = (const float*)d_in[21];
    const float* r2_b3 = (const float*)d_in[22];
    const float* mix2  = (const float*)d_in[23];
    const float* mlp_w0 = (const float*)d_in[24];
    const float* mlp_b0 = (const float*)d_in[25];
    const float* mlp_w1 = (const float*)d_in[26];
    const float* mlp_b1 = (const float*)d_in[27];
    const float* mlp_w2 = (const float*)d_in[28];
    const float* mlp_b2 = (const float*)d_in[29];

    const int SM_P1  = 13376 * 4;
    const int SM_P2  = 13184 * 4;
    const int SM_MLP = (5128 + 4096) * 4;

    cudaFuncSetAttribute(k_phase1, cudaFuncAttributeMaxDynamicSharedMemorySize, SM_P1);
    cudaFuncSetAttribute(k_phase2, cudaFuncAttributeMaxDynamicSharedMemorySize, SM_P2);
    cudaFuncSetAttribute(k_mlp,    cudaFuncAttributeMaxDynamicSharedMemorySize, SM_MLP);
    cudaFuncSetAttribute(k_phase1, cudaFuncAttributePreferredSharedMemoryCarveout, 100);
    cudaFuncSetAttribute(k_phase2, cudaFuncAttributePreferredSharedMemoryCarveout, 100);
    cudaFuncSetAttribute(k_mlp,    cudaFuncAttributePreferredSharedMemoryCarveout, 100);

    k_geom<<<NPAIR/256, 256>>>(frac, cell);
    k_phase1<<<NNODE, 128, SM_P1>>>(w_embed,
        r1_w0, r1_b0, r1_w1, r1_b1, r1_w2, r1_b2, r1_w3, r1_b3,
        mix1_l0, mix1_l1, mix1_l2);
    k_phase2<<<NNODE, 128, SM_P2>>>(
        r2_w0, r2_b0, r2_w1, r2_b1, r2_w2, r2_b2, r2_w3, r2_b3, mix2);
    k_mlp<<<NNODE/8, 512, SM_MLP>>>(tim, mlp_w0, mlp_b0, mlp_w1, mlp_b1,
        mlp_w2, mlp_b2, (float*)d_out);
}